// round 1
// baseline (speedup 1.0000x reference)
#include <cuda_runtime.h>
#include <math.h>

#define Bb   8
#define Tn   2048
#define Dm   512
#define Sn   4
#define GH   64
#define Mtot (Bb*Tn)          // 16384
#define GIN  521              // D + 1 + SE

// ---------------- scratch (static device globals; no runtime allocs) ----------------
__device__ float g_preds[(size_t)Sn*Mtot*Dm];   // [s][m][d]  134MB
__device__ float g_wenc [(size_t)Sn*Mtot*Dm];   // [s][m][d]  134MB
__device__ float g_hgate[(size_t)Sn*Mtot*GH];   // [s][m][h]  16.8MB
__device__ float g_err [Mtot*Sn];               // [(b*T+t)*S+s]
__device__ float g_z   [Mtot*Sn];
__device__ float g_a   [Tn*Sn];                 // mean_b err
__device__ float g_mu  [Tn*Sn];                 // carry mu at t
__device__ float g_mad [Tn*Sn];
__device__ float g_sig [Tn*Sn];                 // carry sigma at t
__device__ float g_g3  [(size_t)Mtot*Sn*3];     // gate for 3 hypothetical states
__device__ float g_g3m [Tn*Sn*3];               // mean_b g3
__device__ int   g_state[Tn*Sn];                // state used at step t
__device__ float g_geff[Mtot*Sn];

// ---------------- 128x128x8 SGEMM: C[s] = A(16384x512) * W[s](512x512) + b[s] ----------------
__global__ void sgemm128(const float* __restrict__ A, const float* __restrict__ W,
                         const float* __restrict__ bias, int which)
{
    const int s = blockIdx.z;
    const float* Wm = W + (size_t)s * Dm * Dm;
    const float* bm = bias + (size_t)s * Dm;
    float* Cm = (which ? g_wenc : g_preds) + (size_t)s * Mtot * Dm;

    __shared__ float As[8][128];
    __shared__ float Bs[8][128];

    const int tid = threadIdx.x;            // 256 threads
    const int rowBlock = blockIdx.y * 128;
    const int colBlock = blockIdx.x * 128;
    const int aRow = tid >> 1, aCol = (tid & 1) << 2;
    const int bRow = tid >> 5, bCol = (tid & 31) << 2;
    const int ty = tid >> 4, tx = tid & 15;

    float acc[8][8];
    #pragma unroll
    for (int i = 0; i < 8; i++)
        #pragma unroll
        for (int j = 0; j < 8; j++) acc[i][j] = 0.f;

    const float* Aptr = A + (size_t)(rowBlock + aRow) * Dm + aCol;
    const float* Bptr = Wm + (size_t)bRow * Dm + colBlock + bCol;

    for (int k0 = 0; k0 < Dm; k0 += 8) {
        float4 av = *(const float4*)(Aptr + k0);
        float4 bv = *(const float4*)(Bptr + (size_t)k0 * Dm);
        As[aCol+0][aRow] = av.x; As[aCol+1][aRow] = av.y;
        As[aCol+2][aRow] = av.z; As[aCol+3][aRow] = av.w;
        *(float4*)&Bs[bRow][bCol] = bv;
        __syncthreads();
        #pragma unroll
        for (int kk = 0; kk < 8; kk++) {
            float4 ra0 = *(float4*)&As[kk][ty*8];
            float4 ra1 = *(float4*)&As[kk][ty*8+4];
            float4 rb0 = *(float4*)&Bs[kk][tx*8];
            float4 rb1 = *(float4*)&Bs[kk][tx*8+4];
            float ra[8] = {ra0.x,ra0.y,ra0.z,ra0.w, ra1.x,ra1.y,ra1.z,ra1.w};
            float rb[8] = {rb0.x,rb0.y,rb0.z,rb0.w, rb1.x,rb1.y,rb1.z,rb1.w};
            #pragma unroll
            for (int i = 0; i < 8; i++)
                #pragma unroll
                for (int j = 0; j < 8; j++) acc[i][j] += ra[i]*rb[j];
        }
        __syncthreads();
    }
    #pragma unroll
    for (int i = 0; i < 8; i++) {
        int r = rowBlock + ty*8 + i;
        int c0 = colBlock + tx*8;
        float4 o0, o1;
        o0.x = acc[i][0]+bm[c0+0]; o0.y = acc[i][1]+bm[c0+1];
        o0.z = acc[i][2]+bm[c0+2]; o0.w = acc[i][3]+bm[c0+3];
        o1.x = acc[i][4]+bm[c0+4]; o1.y = acc[i][5]+bm[c0+5];
        o1.z = acc[i][6]+bm[c0+6]; o1.w = acc[i][7]+bm[c0+7];
        *(float4*)&Cm[(size_t)r*Dm + c0]     = o0;
        *(float4*)&Cm[(size_t)r*Dm + c0 + 4] = o1;
    }
}

// ---------------- gate GEMM: hgate[s] = A(16384x512) * W1[s][0:512,0:64] + b1[s] ----------------
__global__ void sgemm_gate(const float* __restrict__ A, const float* __restrict__ W1,
                           const float* __restrict__ b1)
{
    const int s = blockIdx.z;
    const float* Wm = W1 + (size_t)s * GIN * GH;   // row stride GH
    const float* bm = b1 + (size_t)s * GH;
    float* Cm = g_hgate + (size_t)s * Mtot * GH;

    __shared__ float As[8][128];
    __shared__ float Bs[8][64];

    const int tid = threadIdx.x;
    const int rowBlock = blockIdx.y * 128;
    const int aRow = tid >> 1, aCol = (tid & 1) << 2;
    const int bRow = tid >> 5, bCol = (tid & 31) << 1;    // float2 loads
    const int ty = tid >> 4, tx = tid & 15;

    float acc[8][4];
    #pragma unroll
    for (int i = 0; i < 8; i++)
        #pragma unroll
        for (int j = 0; j < 4; j++) acc[i][j] = 0.f;

    const float* Aptr = A + (size_t)(rowBlock + aRow) * Dm + aCol;

    for (int k0 = 0; k0 < Dm; k0 += 8) {
        float4 av = *(const float4*)(Aptr + k0);
        float2 bv = *(const float2*)(Wm + (size_t)(k0 + bRow) * GH + bCol);
        As[aCol+0][aRow] = av.x; As[aCol+1][aRow] = av.y;
        As[aCol+2][aRow] = av.z; As[aCol+3][aRow] = av.w;
        Bs[bRow][bCol]   = bv.x; Bs[bRow][bCol+1] = bv.y;
        __syncthreads();
        #pragma unroll
        for (int kk = 0; kk < 8; kk++) {
            float4 ra0 = *(float4*)&As[kk][ty*8];
            float4 ra1 = *(float4*)&As[kk][ty*8+4];
            float4 rb  = *(float4*)&Bs[kk][tx*4];
            float ra[8] = {ra0.x,ra0.y,ra0.z,ra0.w, ra1.x,ra1.y,ra1.z,ra1.w};
            float rb4[4] = {rb.x,rb.y,rb.z,rb.w};
            #pragma unroll
            for (int i = 0; i < 8; i++)
                #pragma unroll
                for (int j = 0; j < 4; j++) acc[i][j] += ra[i]*rb4[j];
        }
        __syncthreads();
    }
    #pragma unroll
    for (int i = 0; i < 8; i++) {
        int r = rowBlock + ty*8 + i;
        int c0 = tx*4;
        float4 o;
        o.x = acc[i][0]+bm[c0+0]; o.y = acc[i][1]+bm[c0+1];
        o.z = acc[i][2]+bm[c0+2]; o.w = acc[i][3]+bm[c0+3];
        *(float4*)&Cm[(size_t)r*GH + c0] = o;
    }
}

// ---------------- err[b,t,s] = || preds[b,t-1,s,:] - h[b,t,:] || ----------------
__global__ void err_kernel(const float* __restrict__ h)
{
    int gw = (blockIdx.x * blockDim.x + threadIdx.x) >> 5;
    int lane = threadIdx.x & 31;
    if (gw >= Mtot * Sn) return;
    int s = gw & 3, m = gw >> 2;
    int t = m & (Tn - 1);
    if (t == 0) { if (!lane) g_err[m*Sn + s] = 0.f; return; }
    const float* p  = g_preds + ((size_t)s*Mtot + m - 1) * Dm;
    const float* hh = h + (size_t)m * Dm;
    float acc = 0.f;
    #pragma unroll 4
    for (int d = lane; d < Dm; d += 32) { float df = p[d] - hh[d]; acc += df*df; }
    #pragma unroll
    for (int o = 16; o; o >>= 1) acc += __shfl_down_sync(0xffffffffu, acc, o);
    if (!lane) g_err[m*Sn + s] = sqrtf(acc + 1e-8f);
}

__global__ void errmean_kernel()
{
    int i = blockIdx.x * blockDim.x + threadIdx.x;
    if (i >= Tn * Sn) return;
    int s = i & 3, t = i >> 2;
    float acc = 0.f;
    #pragma unroll
    for (int b = 0; b < Bb; b++) acc += g_err[((size_t)(b*Tn + t))*Sn + s];
    g_a[i] = acc * 0.125f;
}

__global__ void scan_mu_kernel()
{
    __shared__ float sm[Tn*Sn];
    for (int i = threadIdx.x; i < Tn*Sn; i += blockDim.x) sm[i] = g_a[i];
    __syncthreads();
    if (threadIdx.x < Sn) {
        int s = threadIdx.x;
        float mu = 0.f;
        for (int t = 0; t < Tn; t++) {
            g_mu[t*Sn + s] = mu;                      // carry value used at step t
            if (t > 0) mu = 0.99f*mu + 0.01f*sm[t*Sn + s];
        }
    }
}

__global__ void mad_kernel()
{
    int i = blockIdx.x * blockDim.x + threadIdx.x;
    if (i >= Tn * Sn) return;
    int s = i & 3, t = i >> 2;
    float mu = g_mu[i];
    float acc = 0.f;
    #pragma unroll
    for (int b = 0; b < Bb; b++) acc += fabsf(g_err[((size_t)(b*Tn + t))*Sn + s] - mu);
    g_mad[i] = acc * 0.125f;
}

__global__ void scan_sigma_kernel()
{
    __shared__ float sm[Tn*Sn];
    for (int i = threadIdx.x; i < Tn*Sn; i += blockDim.x) sm[i] = g_mad[i];
    __syncthreads();
    if (threadIdx.x < Sn) {
        int s = threadIdx.x;
        float sg = 1.f;
        for (int t = 0; t < Tn; t++) {
            g_sig[t*Sn + s] = sg;
            if (t > 0) sg = 0.99f*sg + 0.01f*sm[t*Sn + s];
        }
    }
}

__global__ void z_kernel()
{
    int i = blockIdx.x * blockDim.x + threadIdx.x;
    if (i >= Mtot * Sn) return;
    int s = i & 3, m = i >> 2;
    int t = m & (Tn - 1);
    g_z[i] = (t == 0) ? 0.f
                      : (g_err[i] - g_mu[t*Sn + s]) / fmaxf(g_sig[t*Sn + s], 1e-3f);
}

// ---------------- gate for all 3 hypothetical states ----------------
__global__ void gate3_kernel(const float* __restrict__ gate_W1, const float* __restrict__ gate_W2,
                             const float* __restrict__ gate_b2, const float* __restrict__ se)
{
    int gw = (blockIdx.x * blockDim.x + threadIdx.x) >> 5;
    int lane = threadIdx.x & 31;
    if (gw >= Mtot * Sn) return;
    int s = gw & 3, m = gw >> 2;
    const float* W1 = gate_W1 + (size_t)s * GIN * GH;
    const float* hb = g_hgate + ((size_t)s*Mtot + m) * GH;
    float zz = g_z[m*Sn + s];
    float base0 = hb[lane]      + zz * W1[512*GH + lane];
    float base1 = hb[lane + 32] + zz * W1[512*GH + lane + 32];
    float se0[3] = {0,0,0}, se1[3] = {0,0,0};
    #pragma unroll
    for (int e = 0; e < 8; e++) {
        float wa = W1[(513+e)*GH + lane];
        float wb = W1[(513+e)*GH + lane + 32];
        #pragma unroll
        for (int st = 0; st < 3; st++) {
            float sv = se[st*8 + e];
            se0[st] += sv * wa; se1[st] += sv * wb;
        }
    }
    float w20 = gate_W2[s*GH + lane], w21 = gate_W2[s*GH + lane + 32];
    float b2 = gate_b2[s];
    #pragma unroll
    for (int st = 0; st < 3; st++) {
        float v = fmaxf(base0 + se0[st], 0.f)*w20 + fmaxf(base1 + se1[st], 0.f)*w21;
        #pragma unroll
        for (int o = 16; o; o >>= 1) v += __shfl_down_sync(0xffffffffu, v, o);
        if (!lane) g_g3[((size_t)m*Sn + s)*3 + st] = 1.f / (1.f + expf(-(v + b2)));
    }
}

__global__ void g3mean_kernel()
{
    int i = blockIdx.x * blockDim.x + threadIdx.x;
    if (i >= Tn*Sn*3) return;
    int st = i % 3, r = i / 3;
    int s = r & 3, t = r >> 2;
    float acc = 0.f;
    #pragma unroll
    for (int b = 0; b < Bb; b++)
        acc += g_g3[(((size_t)b*Tn + t)*Sn + s)*3 + st];
    g_g3m[i] = acc * 0.125f;
}

// ---------------- gate_ema / state machine scan (2-phase smem staging, 48KB) ----------------
__global__ void state_scan_kernel()
{
    __shared__ float sm[12288];   // 1024 timesteps * 4 slots * 3 states
    float ema = 0.5f; int cur = 0;
    for (int ph = 0; ph < 2; ph++) {
        __syncthreads();
        for (int i = threadIdx.x; i < 12288; i += blockDim.x) sm[i] = g_g3m[ph*12288 + i];
        __syncthreads();
        if (threadIdx.x < Sn) {
            int s = threadIdx.x;
            for (int tt = 0; tt < 1024; tt++) {
                int t = ph*1024 + tt;
                g_state[t*Sn + s] = cur;              // state used at step t
                float gm = sm[(tt*Sn + s)*3 + cur];
                ema = 0.99f*ema + 0.01f*gm;
                if (cur == 0)      { if (ema < 0.1f)  cur = 1; }
                else if (cur == 1) { if (ema < 0.03f) cur = 2; else if (ema > 0.25f) cur = 0; }
                else               { if (ema > 0.25f) cur = 0; }
            }
        }
    }
}

__global__ void geff_kernel()
{
    int i = blockIdx.x * blockDim.x + threadIdx.x;
    if (i >= Mtot * Sn) return;
    int s = i & 3, m = i >> 2;
    int t = m & (Tn - 1);
    int st = g_state[t*Sn + s];
    float gn = (st == 0) ? 1.0f : ((st == 1) ? 0.5f : 0.1f);
    g_geff[i] = g_g3[(size_t)i*3 + st] * gn;
}

// ---------------- m recurrence: thread per (b,s,d4), stream over t ----------------
__global__ void mscan_kernel(const float* __restrict__ w0, float* __restrict__ out)
{
    int blk = blockIdx.x;          // 128 blocks
    int q = blk & 3;
    int bs = blk >> 2;
    int s = bs & 3, b = bs >> 2;
    int lane = threadIdx.x;        // 32
    int d4 = q*32 + lane;          // float4 index within D (0..127)

    const float4* wp = (const float4*)g_wenc + ((size_t)s*Mtot + (size_t)b*Tn)*(Dm/4) + d4;
    float4* op = (float4*)out + ((size_t)b*Tn)*(Sn*Dm/4) + s*(Dm/4) + d4;
    const float* gp = g_geff + ((size_t)b*Tn)*Sn + s;

    float4 m = ((const float4*)w0)[s*(Dm/4) + d4];
    #pragma unroll 4
    for (int t = 0; t < Tn; t++) {
        float ge = __ldg(gp + (size_t)t*Sn);
        float4 w = __ldg(wp + (size_t)t*(Dm/4));
        float om = 1.f - ge;
        m.x = om*m.x + ge*w.x;
        m.y = om*m.y + ge*w.y;
        m.z = om*m.z + ge*w.z;
        m.w = om*m.w + ge*w.w;
        op[(size_t)t*(Sn*Dm/4)] = m;
    }
}

// ---------------- launch ----------------
extern "C" void kernel_launch(void* const* d_in, const int* in_sizes, int n_in,
                              void* d_out, int out_size)
{
    const float* h        = (const float*)d_in[0];
    const float* pred_W   = (const float*)d_in[1];
    const float* pred_b   = (const float*)d_in[2];
    const float* gate_W1  = (const float*)d_in[3];
    const float* gate_b1  = (const float*)d_in[4];
    const float* gate_W2  = (const float*)d_in[5];
    const float* gate_b2  = (const float*)d_in[6];
    const float* write_W  = (const float*)d_in[7];
    const float* write_b  = (const float*)d_in[8];
    const float* w0       = (const float*)d_in[9];
    const float* st_embed = (const float*)d_in[10];
    float* out = (float*)d_out;

    dim3 gBig(Dm/128, Mtot/128, Sn);
    sgemm128<<<gBig, 256>>>(h, pred_W, pred_b, 0);
    sgemm128<<<gBig, 256>>>(h, write_W, write_b, 1);
    sgemm_gate<<<dim3(1, Mtot/128, Sn), 256>>>(h, gate_W1, gate_b1);

    err_kernel<<<(Mtot*Sn*32 + 255)/256, 256>>>(h);
    errmean_kernel<<<(Tn*Sn + 255)/256, 256>>>();
    scan_mu_kernel<<<1, 256>>>();
    mad_kernel<<<(Tn*Sn + 255)/256, 256>>>();
    scan_sigma_kernel<<<1, 256>>>();
    z_kernel<<<(Mtot*Sn + 255)/256, 256>>>();

    gate3_kernel<<<(Mtot*Sn*32 + 255)/256, 256>>>(gate_W1, gate_W2, gate_b2, st_embed);
    g3mean_kernel<<<(Tn*Sn*3 + 255)/256, 256>>>();
    state_scan_kernel<<<1, 256>>>();
    geff_kernel<<<(Mtot*Sn + 255)/256, 256>>>();

    mscan_kernel<<<Bb*Sn*4, 32>>>(w0, out);
}

// round 3
// speedup vs baseline: 1.6843x; 1.6843x over previous
#include <cuda_runtime.h>
#include <cuda_bf16.h>
#include <math.h>
#include <stdint.h>

#define Bb   8
#define Tn   2048
#define Dm   512
#define Sn   4
#define GH   64
#define Mtot (Bb*Tn)          // 16384
#define NCOMB 1088            // 512 pred | 512 wenc | 64 gate-hidden
#define KEXT  1024            // 512 hi | 512 lo

// ---------------- scratch (static device globals) ----------------
__device__ __nv_bfloat16 g_Abf[(size_t)Mtot*KEXT];        // [m][k]
__device__ __nv_bfloat16 g_Bbf[(size_t)Sn*NCOMB*KEXT];    // [s][n][k]
__device__ float g_preds[(size_t)Sn*Mtot*Dm];
__device__ float g_wenc [(size_t)Sn*Mtot*Dm];
__device__ float g_hgate[(size_t)Sn*Mtot*GH];
__device__ float g_err [Mtot*Sn];
__device__ float g_z   [Mtot*Sn];
__device__ float g_a   [Tn*Sn];
__device__ float g_mu  [Tn*Sn];
__device__ float g_mad [Tn*Sn];
__device__ float g_sig [Tn*Sn];
__device__ float g_g3  [(size_t)Mtot*Sn*3];
__device__ float g_g3m [Tn*Sn*3];
__device__ int   g_state[Tn*Sn];
__device__ float g_geff[Mtot*Sn];

// ---------------- prep: fp32 -> bf16 hi/lo split ----------------
__global__ void convA_kernel(const float* __restrict__ h)
{
    int i = blockIdx.x * blockDim.x + threadIdx.x;
    if (i >= Mtot * Dm) return;
    int m = i >> 9, d = i & 511;
    float a = h[i];
    __nv_bfloat16 hi = __float2bfloat16(a);
    float lo = a - __bfloat162float(hi);
    g_Abf[(size_t)m*KEXT + d]       = hi;
    g_Abf[(size_t)m*KEXT + 512 + d] = __float2bfloat16(lo);
}

__global__ void convB_kernel(const float* __restrict__ pred_W, const float* __restrict__ write_W,
                             const float* __restrict__ gate_W1)
{
    int i = blockIdx.x * blockDim.x + threadIdx.x;
    if (i >= Sn * NCOMB * Dm) return;
    int d = i & 511;
    int r = i >> 9;
    int n = r % NCOMB;
    int s = r / NCOMB;
    float v;
    if (n < 512)       v = pred_W [((size_t)s*512 + d)*512 + n];
    else if (n < 1024) v = write_W[((size_t)s*512 + d)*512 + (n - 512)];
    else               v = gate_W1[((size_t)s*521 + d)*64  + (n - 1024)];
    __nv_bfloat16 hi = __float2bfloat16(v);
    float lo = v - __bfloat162float(hi);
    size_t base = ((size_t)s*NCOMB + n) * KEXT;
    g_Bbf[base + d]       = hi;
    g_Bbf[base + 512 + d] = __float2bfloat16(lo);
}

// ================= mma.sync helpers =================
__device__ __forceinline__ uint32_t smem_u32(const void* p) {
    uint32_t a;
    asm("{ .reg .u64 t; cvta.to.shared.u64 t, %1; cvt.u32.u64 %0, t; }" : "=r"(a) : "l"(p));
    return a;
}
#define CP16(dst, src) asm volatile("cp.async.cg.shared.global [%0], [%1], 16;" :: "r"(dst), "l"(src))
#define CP_COMMIT()    asm volatile("cp.async.commit_group;" ::: "memory")
#define CP_WAIT1()     asm volatile("cp.async.wait_group 1;" ::: "memory")
#define LDSM4(r0,r1,r2,r3,addr) \
    asm volatile("ldmatrix.sync.aligned.m8n8.x4.shared.b16 {%0,%1,%2,%3}, [%4];" \
        : "=r"(r0),"=r"(r1),"=r"(r2),"=r"(r3) : "r"(addr))
#define MMA16816(d, a, b) \
    asm volatile("mma.sync.aligned.m16n8k16.row.col.f32.bf16.bf16.f32 " \
        "{%0,%1,%2,%3},{%4,%5,%6,%7},{%8,%9},{%0,%1,%2,%3};" \
        : "+f"((d)[0]),"+f"((d)[1]),"+f"((d)[2]),"+f"((d)[3]) \
        : "r"((a)[0]),"r"((a)[1]),"r"((a)[2]),"r"((a)[3]), "r"((b)[0]),"r"((b)[1]))

// smem tile: pitch 40 bf16 (80B) per row; A/B 128 rows, double buffered
#define PITCH 40
#define TILEB (128*PITCH)     // bf16 elements per tile buffer

// CFG 0: big GEMM (N-tile 128, warp tile 64x32, MA=4)
// CFG 1: gate GEMM (N=64, warp tile 32x32, MA=2)
template<int CFG>
__global__ void __launch_bounds__(256, 2)
gemm_mma(const float* __restrict__ pred_b, const float* __restrict__ write_b,
         const float* __restrict__ gate_b1)
{
    constexpr int MA = CFG ? 2 : 4;
    constexpr int BROWS = CFG ? 64 : 128;

    __shared__ __align__(16) __nv_bfloat16 sA[2*TILEB];
    __shared__ __align__(16) __nv_bfloat16 sB[2*TILEB];

    const int tid = threadIdx.x;
    const int wid = tid >> 5, lane = tid & 31;
    const int s = blockIdx.z;
    const int mbase = blockIdx.y * 128;

    int which, nbase, colbase;
    if (CFG == 0) {
        which = blockIdx.x >> 2;                 // 0: preds, 1: wenc
        int nt = blockIdx.x & 3;
        nbase = which * 512 + nt * 128;          // row into combined B
        colbase = nt * 128;
    } else {
        which = 2; nbase = 1024; colbase = 0;
    }

    int mw, nw;
    if (CFG == 0) { mw = wid >> 2; nw = wid & 3; }
    else          { mw = wid >> 1; nw = wid & 1; }
    const int m0 = mw * (MA*16);
    const int n0 = nw * 32;

    const uint32_t sAu = smem_u32(sA);
    const uint32_t sBu = smem_u32(sB);

    // per-lane ldmatrix smem addresses (byte offsets within a buffer)
    const int idx = lane & 7, sel = lane >> 3;
    // A: row = m0 + (sel&1)*8 + idx + i*16 ; k = (sel>>1)*8 + k0
    const uint32_t aAddrBase = sAu + (uint32_t)(m0 + (sel&1)*8 + idx) * (PITCH*2) + (uint32_t)((sel>>1)*8)*2;
    // B: row = n0 + j*16 + (sel>>1)*8 + idx ; k = (sel&1)*8 + k0
    const uint32_t bAddrBase = sBu + (uint32_t)(n0 + (sel>>1)*8 + idx) * (PITCH*2) + (uint32_t)((sel&1)*8)*2;

    float acc[MA][4][4];
    #pragma unroll
    for (int i = 0; i < MA; i++)
        #pragma unroll
        for (int j = 0; j < 4; j++)
            #pragma unroll
            for (int q = 0; q < 4; q++) acc[i][j][q] = 0.f;

    const char* Aall = (const char*)g_Abf;
    const char* Ball = (const char*)g_Bbf;

    auto load_tile = [&](int c, int buf) {
        const int p = c >> 4, kk = (c & 15) * 32;
        const int acol = ((p == 2) ? 512 : 0) + kk;
        const int bcol = ((p == 1) ? 512 : 0) + kk;
        const uint32_t ab = sAu + buf * (TILEB*2);
        const uint32_t bb = sBu + buf * (TILEB*2);
        #pragma unroll
        for (int it = 0; it < 2; it++) {
            int g = tid + it*256;                 // 512 granules: row*4 + gc
            int row = g >> 2, gc = g & 3;
            CP16(ab + row*(PITCH*2) + gc*16,
                 Aall + ((size_t)(mbase + row)*KEXT + acol + gc*8)*2);
        }
        #pragma unroll
        for (int it = 0; it < BROWS/64; it++) {
            int g = tid + it*256;
            int row = g >> 2, gc = g & 3;
            CP16(bb + row*(PITCH*2) + gc*16,
                 Ball + (((size_t)s*NCOMB + nbase + row)*KEXT + bcol + gc*8)*2);
        }
        CP_COMMIT();
    };

    load_tile(0, 0);
    for (int c = 0; c < 48; c++) {
        const int buf = c & 1;
        if (c + 1 < 48) load_tile(c + 1, (c + 1) & 1);
        else CP_COMMIT();
        CP_WAIT1();
        __syncthreads();
        const uint32_t aOff = aAddrBase + buf*(TILEB*2);
        const uint32_t bOff = bAddrBase + buf*(TILEB*2);
        #pragma unroll
        for (int ks = 0; ks < 2; ks++) {
            uint32_t afr[MA][4], bfr[4][2];
            #pragma unroll
            for (int i = 0; i < MA; i++)
                LDSM4(afr[i][0], afr[i][1], afr[i][2], afr[i][3],
                      aOff + i*16*(PITCH*2) + ks*32);
            #pragma unroll
            for (int jp = 0; jp < 2; jp++) {
                uint32_t r0, r1, r2, r3;
                LDSM4(r0, r1, r2, r3, bOff + jp*16*(PITCH*2) + ks*32);
                bfr[jp*2+0][0] = r0; bfr[jp*2+0][1] = r1;
                bfr[jp*2+1][0] = r2; bfr[jp*2+1][1] = r3;
            }
            #pragma unroll
            for (int i = 0; i < MA; i++)
                #pragma unroll
                for (int j = 0; j < 4; j++)
                    MMA16816(acc[i][j], afr[i], bfr[j]);
        }
        __syncthreads();
    }

    // epilogue: bias + store
    float* Cm; const float* bias; int stride;
    if (which == 0) { Cm = g_preds + (size_t)s*Mtot*Dm; bias = pred_b  + s*Dm; stride = Dm; }
    else if (which == 1) { Cm = g_wenc + (size_t)s*Mtot*Dm; bias = write_b + s*Dm; stride = Dm; }
    else { Cm = g_hgate + (size_t)s*Mtot*GH; bias = gate_b1 + s*GH; stride = GH; }

    const int rbase = mbase + m0 + (lane >> 2);
    const int cbase = colbase + n0 + (lane & 3) * 2;
    #pragma unroll
    for (int j = 0; j < 4; j++) {
        const int col = cbase + j*8;
        const float b0 = __ldg(bias + col), b1 = __ldg(bias + col + 1);
        #pragma unroll
        for (int i = 0; i < MA; i++) {
            const int r = rbase + i*16;
            float2 o0 = { acc[i][j][0] + b0, acc[i][j][1] + b1 };
            float2 o1 = { acc[i][j][2] + b0, acc[i][j][3] + b1 };
            *(float2*)(Cm + (size_t)r*stride + col)       = o0;
            *(float2*)(Cm + (size_t)(r+8)*stride + col)   = o1;
        }
    }
}

// ---------------- err[b,t,s] = || preds[b,t-1,s,:] - h[b,t,:] || ----------------
__global__ void err_kernel(const float* __restrict__ h)
{
    int gw = (blockIdx.x * blockDim.x + threadIdx.x) >> 5;
    int lane = threadIdx.x & 31;
    if (gw >= Mtot * Sn) return;
    int s = gw & 3, m = gw >> 2;
    int t = m & (Tn - 1);
    if (t == 0) { if (!lane) g_err[m*Sn + s] = 0.f; return; }
    const float* p  = g_preds + ((size_t)s*Mtot + m - 1) * Dm;
    const float* hh = h + (size_t)m * Dm;
    float acc = 0.f;
    #pragma unroll 4
    for (int d = lane; d < Dm; d += 32) { float df = p[d] - hh[d]; acc += df*df; }
    #pragma unroll
    for (int o = 16; o; o >>= 1) acc += __shfl_down_sync(0xffffffffu, acc, o);
    if (!lane) g_err[m*Sn + s] = sqrtf(acc + 1e-8f);
}

__global__ void errmean_kernel()
{
    int i = blockIdx.x * blockDim.x + threadIdx.x;
    if (i >= Tn * Sn) return;
    int s = i & 3, t = i >> 2;
    float acc = 0.f;
    #pragma unroll
    for (int b = 0; b < Bb; b++) acc += g_err[((size_t)(b*Tn + t))*Sn + s];
    g_a[i] = acc * 0.125f;
}

__global__ void scan_mu_kernel()
{
    __shared__ float sm[Tn*Sn];
    for (int i = threadIdx.x; i < Tn*Sn; i += blockDim.x) sm[i] = g_a[i];
    __syncthreads();
    if (threadIdx.x < Sn) {
        int s = threadIdx.x;
        float mu = 0.f;
        for (int t = 0; t < Tn; t++) {
            g_mu[t*Sn + s] = mu;
            if (t > 0) mu = 0.99f*mu + 0.01f*sm[t*Sn + s];
        }
    }
}

__global__ void mad_kernel()
{
    int i = blockIdx.x * blockDim.x + threadIdx.x;
    if (i >= Tn * Sn) return;
    int s = i & 3, t = i >> 2;
    float mu = g_mu[i];
    float acc = 0.f;
    #pragma unroll
    for (int b = 0; b < Bb; b++) acc += fabsf(g_err[((size_t)(b*Tn + t))*Sn + s] - mu);
    g_mad[i] = acc * 0.125f;
}

__global__ void scan_sigma_kernel()
{
    __shared__ float sm[Tn*Sn];
    for (int i = threadIdx.x; i < Tn*Sn; i += blockDim.x) sm[i] = g_mad[i];
    __syncthreads();
    if (threadIdx.x < Sn) {
        int s = threadIdx.x;
        float sg = 1.f;
        for (int t = 0; t < Tn; t++) {
            g_sig[t*Sn + s] = sg;
            if (t > 0) sg = 0.99f*sg + 0.01f*sm[t*Sn + s];
        }
    }
}

__global__ void z_kernel()
{
    int i = blockIdx.x * blockDim.x + threadIdx.x;
    if (i >= Mtot * Sn) return;
    int s = i & 3, m = i >> 2;
    int t = m & (Tn - 1);
    g_z[i] = (t == 0) ? 0.f
                      : (g_err[i] - g_mu[t*Sn + s]) / fmaxf(g_sig[t*Sn + s], 1e-3f);
}

// ---------------- gate for all 3 hypothetical states ----------------
__global__ void gate3_kernel(const float* __restrict__ gate_W1, const float* __restrict__ gate_W2,
                             const float* __restrict__ gate_b2, const float* __restrict__ se)
{
    int gw = (blockIdx.x * blockDim.x + threadIdx.x) >> 5;
    int lane = threadIdx.x & 31;
    if (gw >= Mtot * Sn) return;
    int s = gw & 3, m = gw >> 2;
    const float* W1 = gate_W1 + (size_t)s * 521 * GH;
    const float* hb = g_hgate + ((size_t)s*Mtot + m) * GH;
    float zz = g_z[m*Sn + s];
    float base0 = hb[lane]      + zz * W1[512*GH + lane];
    float base1 = hb[lane + 32] + zz * W1[512*GH + lane + 32];
    float se0[3] = {0,0,0}, se1[3] = {0,0,0};
    #pragma unroll
    for (int e = 0; e < 8; e++) {
        float wa = W1[(513+e)*GH + lane];
        float wb = W1[(513+e)*GH + lane + 32];
        #pragma unroll
        for (int st = 0; st < 3; st++) {
            float sv = se[st*8 + e];
            se0[st] += sv * wa; se1[st] += sv * wb;
        }
    }
    float w20 = gate_W2[s*GH + lane], w21 = gate_W2[s*GH + lane + 32];
    float b2 = gate_b2[s];
    #pragma unroll
    for (int st = 0; st < 3; st++) {
        float v = fmaxf(base0 + se0[st], 0.f)*w20 + fmaxf(base1 + se1[st], 0.f)*w21;
        #pragma unroll
        for (int o = 16; o; o >>= 1) v += __shfl_down_sync(0xffffffffu, v, o);
        if (!lane) g_g3[((size_t)m*Sn + s)*3 + st] = 1.f / (1.f + expf(-(v + b2)));
    }
}

__global__ void g3mean_kernel()
{
    int i = blockIdx.x * blockDim.x + threadIdx.x;
    if (i >= Tn*Sn*3) return;
    int st = i % 3, r = i / 3;
    int s = r & 3, t = r >> 2;
    float acc = 0.f;
    #pragma unroll
    for (int b = 0; b < Bb; b++)
        acc += g_g3[(((size_t)b*Tn + t)*Sn + s)*3 + st];
    g_g3m[i] = acc * 0.125f;
}

__global__ void state_scan_kernel()
{
    __shared__ float sm[12288];
    float ema = 0.5f; int cur = 0;
    for (int ph = 0; ph < 2; ph++) {
        __syncthreads();
        for (int i = threadIdx.x; i < 12288; i += blockDim.x) sm[i] = g_g3m[ph*12288 + i];
        __syncthreads();
        if (threadIdx.x < Sn) {
            int s = threadIdx.x;
            for (int tt = 0; tt < 1024; tt++) {
                int t = ph*1024 + tt;
                g_state[t*Sn + s] = cur;
                float gm = sm[(tt*Sn + s)*3 + cur];
                ema = 0.99f*ema + 0.01f*gm;
                if (cur == 0)      { if (ema < 0.1f)  cur = 1; }
                else if (cur == 1) { if (ema < 0.03f) cur = 2; else if (ema > 0.25f) cur = 0; }
                else               { if (ema > 0.25f) cur = 0; }
            }
        }
    }
}

__global__ void geff_kernel()
{
    int i = blockIdx.x * blockDim.x + threadIdx.x;
    if (i >= Mtot * Sn) return;
    int s = i & 3, m = i >> 2;
    int t = m & (Tn - 1);
    int st = g_state[t*Sn + s];
    float gn = (st == 0) ? 1.0f : ((st == 1) ? 0.5f : 0.1f);
    g_geff[i] = g_g3[(size_t)i*3 + st] * gn;
}

// ---------------- m recurrence ----------------
__global__ void mscan_kernel(const float* __restrict__ w0, float* __restrict__ out)
{
    int blk = blockIdx.x;
    int q = blk & 3;
    int bs = blk >> 2;
    int s = bs & 3, b = bs >> 2;
    int lane = threadIdx.x;
    int d4 = q*32 + lane;

    const float4* wp = (const float4*)g_wenc + ((size_t)s*Mtot + (size_t)b*Tn)*(Dm/4) + d4;
    float4* op = (float4*)out + ((size_t)b*Tn)*(Sn*Dm/4) + s*(Dm/4) + d4;
    const float* gp = g_geff + ((size_t)b*Tn)*Sn + s;

    float4 m = ((const float4*)w0)[s*(Dm/4) + d4];
    #pragma unroll 4
    for (int t = 0; t < Tn; t++) {
        float ge = __ldg(gp + (size_t)t*Sn);
        float4 w = __ldg(wp + (size_t)t*(Dm/4));
        float om = 1.f - ge;
        m.x = om*m.x + ge*w.x;
        m.y = om*m.y + ge*w.y;
        m.z = om*m.z + ge*w.z;
        m.w = om*m.w + ge*w.w;
        op[(size_t)t*(Sn*Dm/4)] = m;
    }
}

// ---------------- launch ----------------
extern "C" void kernel_launch(void* const* d_in, const int* in_sizes, int n_in,
                              void* d_out, int out_size)
{
    const float* h        = (const float*)d_in[0];
    const float* pred_W   = (const float*)d_in[1];
    const float* pred_b   = (const float*)d_in[2];
    const float* gate_W1  = (const float*)d_in[3];
    const float* gate_b1  = (const float*)d_in[4];
    const float* gate_W2  = (const float*)d_in[5];
    const float* gate_b2  = (const float*)d_in[6];
    const float* write_W  = (const float*)d_in[7];
    const float* write_b  = (const float*)d_in[8];
    const float* w0       = (const float*)d_in[9];
    const float* st_embed = (const float*)d_in[10];
    float* out = (float*)d_out;

    convA_kernel<<<(Mtot*Dm + 255)/256, 256>>>(h);
    convB_kernel<<<(Sn*NCOMB*Dm + 255)/256, 256>>>(pred_W, write_W, gate_W1);

    gemm_mma<0><<<dim3(8, 128, Sn), 256>>>(pred_b, write_b, gate_b1);
    gemm_mma<1><<<dim3(1, 128, Sn), 256>>>(pred_b, write_b, gate_b1);

    err_kernel<<<(Mtot*Sn*32 + 255)/256, 256>>>(h);
    errmean_kernel<<<(Tn*Sn + 255)/256, 256>>>();
    scan_mu_kernel<<<1, 256>>>();
    mad_kernel<<<(Tn*Sn + 255)/256, 256>>>();
    scan_sigma_kernel<<<1, 256>>>();
    z_kernel<<<(Mtot*Sn + 255)/256, 256>>>();

    gate3_kernel<<<(Mtot*Sn*32 + 255)/256, 256>>>(gate_W1, gate_W2, gate_b2, st_embed);
    g3mean_kernel<<<(Tn*Sn*3 + 255)/256, 256>>>();
    state_scan_kernel<<<1, 256>>>();
    geff_kernel<<<(Mtot*Sn + 255)/256, 256>>>();

    mscan_kernel<<<Bb*Sn*4, 32>>>(w0, out);
}

// round 4
// speedup vs baseline: 1.8190x; 1.0799x over previous
#include <cuda_runtime.h>
#include <cuda_bf16.h>
#include <math.h>
#include <stdint.h>

#define Bb   8
#define Tn   2048
#define Dm   512
#define Sn   4
#define GH   64
#define Mtot (Bb*Tn)          // 16384
#define NCOMB 1088            // 512 pred | 512 wenc | 64 gate-hidden
#define KEXT  1024            // 512 hi | 512 lo

// ---------------- scratch (static device globals) ----------------
__device__ __nv_bfloat16 g_Abf[(size_t)Mtot*KEXT];        // [m][k]
__device__ __nv_bfloat16 g_Bbf[(size_t)Sn*NCOMB*KEXT];    // [s][n][k]
__device__ float g_preds[(size_t)Sn*Mtot*Dm];
__device__ float g_wenc [(size_t)Sn*Mtot*Dm];
__device__ float g_hgate[(size_t)Sn*Mtot*GH];
__device__ float g_err [Mtot*Sn];
__device__ float g_z   [Mtot*Sn];
__device__ float g_a   [Tn*Sn];
__device__ float g_mu  [Tn*Sn];
__device__ float g_mad [Tn*Sn];
__device__ float g_sig [Tn*Sn];
__device__ float g_g3  [(size_t)Mtot*Sn*3];
__device__ float g_g3m [Tn*Sn*3];
__device__ int   g_state[Tn*Sn];
__device__ float g_geff[Mtot*Sn];

// ---------------- prep: fp32 -> bf16 hi/lo split ----------------
__global__ void convA_kernel(const float* __restrict__ h)
{
    int i = blockIdx.x * blockDim.x + threadIdx.x;
    if (i >= Mtot * Dm) return;
    int m = i >> 9, d = i & 511;
    float a = h[i];
    __nv_bfloat16 hi = __float2bfloat16(a);
    float lo = a - __bfloat162float(hi);
    g_Abf[(size_t)m*KEXT + d]       = hi;
    g_Abf[(size_t)m*KEXT + 512 + d] = __float2bfloat16(lo);
}

__global__ void convB_kernel(const float* __restrict__ pred_W, const float* __restrict__ write_W,
                             const float* __restrict__ gate_W1)
{
    int i = blockIdx.x * blockDim.x + threadIdx.x;
    if (i >= Sn * NCOMB * Dm) return;
    int d = i & 511;
    int r = i >> 9;
    int n = r % NCOMB;
    int s = r / NCOMB;
    float v;
    if (n < 512)       v = pred_W [((size_t)s*512 + d)*512 + n];
    else if (n < 1024) v = write_W[((size_t)s*512 + d)*512 + (n - 512)];
    else               v = gate_W1[((size_t)s*521 + d)*64  + (n - 1024)];
    __nv_bfloat16 hi = __float2bfloat16(v);
    float lo = v - __bfloat162float(hi);
    size_t base = ((size_t)s*NCOMB + n) * KEXT;
    g_Bbf[base + d]       = hi;
    g_Bbf[base + 512 + d] = __float2bfloat16(lo);
}

// ================= mma.sync helpers =================
__device__ __forceinline__ uint32_t smem_u32(const void* p) {
    uint32_t a;
    asm("{ .reg .u64 t; cvta.to.shared.u64 t, %1; cvt.u32.u64 %0, t; }" : "=r"(a) : "l"(p));
    return a;
}
#define CP16(dst, src) asm volatile("cp.async.cg.shared.global [%0], [%1], 16;" :: "r"(dst), "l"(src))
#define CP_COMMIT()    asm volatile("cp.async.commit_group;" ::: "memory")
#define CP_WAIT1()     asm volatile("cp.async.wait_group 1;" ::: "memory")
#define LDSM4(r0,r1,r2,r3,addr) \
    asm volatile("ldmatrix.sync.aligned.m8n8.x4.shared.b16 {%0,%1,%2,%3}, [%4];" \
        : "=r"(r0),"=r"(r1),"=r"(r2),"=r"(r3) : "r"(addr))
#define MMA16816(d, a, b) \
    asm volatile("mma.sync.aligned.m16n8k16.row.col.f32.bf16.bf16.f32 " \
        "{%0,%1,%2,%3},{%4,%5,%6,%7},{%8,%9},{%0,%1,%2,%3};" \
        : "+f"((d)[0]),"+f"((d)[1]),"+f"((d)[2]),"+f"((d)[3]) \
        : "r"((a)[0]),"r"((a)[1]),"r"((a)[2]),"r"((a)[3]), "r"((b)[0]),"r"((b)[1]))

// smem tile: k-tile 64, pitch 72 bf16 (144B) per row -> conflict-free ldmatrix
#define PITCH    72
#define ROWB     (PITCH*2)          // 144 bytes per row
#define ATILE_B  (128*ROWB)         // 18432 bytes

// CFG 0: big GEMM (N-tile 128, warp tile 64x32, MA=4)
// CFG 1: gate GEMM (N=64, warp tile 32x32, MA=2)
template<int CFG>
__global__ void __launch_bounds__(256, 2)
gemm_mma(const float* __restrict__ pred_b, const float* __restrict__ write_b,
         const float* __restrict__ gate_b1)
{
    constexpr int MA = CFG ? 2 : 4;
    constexpr int BROWS = CFG ? 64 : 128;
    constexpr int BTILE_B = BROWS * ROWB;
    // layout: A0 | A1 | B0 | B1
    extern __shared__ __align__(16) char smem[];
    const uint32_t sAu = smem_u32(smem);
    const uint32_t sBu = sAu + 2*ATILE_B;

    const int tid = threadIdx.x;
    const int wid = tid >> 5, lane = tid & 31;
    const int s = blockIdx.z;
    const int mbase = blockIdx.y * 128;

    int which, nbase, colbase;
    if (CFG == 0) {
        which = blockIdx.x >> 2;                 // 0: preds, 1: wenc
        int nt = blockIdx.x & 3;
        nbase = which * 512 + nt * 128;
        colbase = nt * 128;
    } else {
        which = 2; nbase = 1024; colbase = 0;
    }

    int mw, nw;
    if (CFG == 0) { mw = wid >> 2; nw = wid & 3; }
    else          { mw = wid >> 1; nw = wid & 1; }
    const int m0 = mw * (MA*16);
    const int n0 = nw * 32;

    // per-lane ldmatrix smem addresses (byte offsets within a buffer)
    const int idx = lane & 7, sel = lane >> 3;
    const uint32_t aAddrBase = sAu + (uint32_t)(m0 + (sel&1)*8 + idx) * ROWB + (uint32_t)((sel>>1)*8)*2;
    const uint32_t bAddrBase = sBu + (uint32_t)(n0 + (sel>>1)*8 + idx) * ROWB + (uint32_t)((sel&1)*8)*2;

    float acc[MA][4][4];
    #pragma unroll
    for (int i = 0; i < MA; i++)
        #pragma unroll
        for (int j = 0; j < 4; j++)
            #pragma unroll
            for (int q = 0; q < 4; q++) acc[i][j][q] = 0.f;

    const char* Aall = (const char*)g_Abf;
    const char* Ball = (const char*)g_Bbf;

    // chunk c in [0,24): pass p = c>>3, k offset (c&7)*64
    auto load_tile = [&](int c, int buf) {
        const int p = c >> 3, kk = (c & 7) * 64;
        const int acol = ((p == 2) ? 512 : 0) + kk;
        const int bcol = ((p == 1) ? 512 : 0) + kk;
        const uint32_t ab = sAu + buf * ATILE_B;
        const uint32_t bb = sBu + buf * BTILE_B;
        #pragma unroll
        for (int it = 0; it < 4; it++) {
            int g = tid + it*256;                 // 1024 granules: row*8 + gc
            int row = g >> 3, gc = g & 7;
            CP16(ab + row*ROWB + gc*16,
                 Aall + ((size_t)(mbase + row)*KEXT + acol + gc*8)*2);
        }
        #pragma unroll
        for (int it = 0; it < BROWS/32; it++) {
            int g = tid + it*256;
            int row = g >> 3, gc = g & 7;
            CP16(bb + row*ROWB + gc*16,
                 Ball + (((size_t)s*NCOMB + nbase + row)*KEXT + bcol + gc*8)*2);
        }
        CP_COMMIT();
    };

    load_tile(0, 0);
    for (int c = 0; c < 24; c++) {
        const int buf = c & 1;
        if (c + 1 < 24) load_tile(c + 1, (c + 1) & 1);
        else CP_COMMIT();
        CP_WAIT1();
        __syncthreads();
        const uint32_t aOff = aAddrBase + buf*ATILE_B;
        const uint32_t bOff = bAddrBase + buf*BTILE_B;
        #pragma unroll
        for (int ks = 0; ks < 4; ks++) {
            uint32_t afr[MA][4], bfr[4][2];
            #pragma unroll
            for (int i = 0; i < MA; i++)
                LDSM4(afr[i][0], afr[i][1], afr[i][2], afr[i][3],
                      aOff + i*16*ROWB + ks*32);
            #pragma unroll
            for (int jp = 0; jp < 2; jp++) {
                uint32_t r0, r1, r2, r3;
                LDSM4(r0, r1, r2, r3, bOff + jp*16*ROWB + ks*32);
                bfr[jp*2+0][0] = r0; bfr[jp*2+0][1] = r1;
                bfr[jp*2+1][0] = r2; bfr[jp*2+1][1] = r3;
            }
            #pragma unroll
            for (int i = 0; i < MA; i++)
                #pragma unroll
                for (int j = 0; j < 4; j++)
                    MMA16816(acc[i][j], afr[i], bfr[j]);
        }
        __syncthreads();
    }

    // epilogue: bias + store
    float* Cm; const float* bias; int stride;
    if (which == 0) { Cm = g_preds + (size_t)s*Mtot*Dm; bias = pred_b  + s*Dm; stride = Dm; }
    else if (which == 1) { Cm = g_wenc + (size_t)s*Mtot*Dm; bias = write_b + s*Dm; stride = Dm; }
    else { Cm = g_hgate + (size_t)s*Mtot*GH; bias = gate_b1 + s*GH; stride = GH; }

    const int rbase = mbase + m0 + (lane >> 2);
    const int cbase = colbase + n0 + (lane & 3) * 2;
    #pragma unroll
    for (int j = 0; j < 4; j++) {
        const int col = cbase + j*8;
        const float b0 = __ldg(bias + col), b1 = __ldg(bias + col + 1);
        #pragma unroll
        for (int i = 0; i < MA; i++) {
            const int r = rbase + i*16;
            float2 o0 = { acc[i][j][0] + b0, acc[i][j][1] + b1 };
            float2 o1 = { acc[i][j][2] + b0, acc[i][j][3] + b1 };
            *(float2*)(Cm + (size_t)r*stride + col)       = o0;
            *(float2*)(Cm + (size_t)(r+8)*stride + col)   = o1;
        }
    }
}

// ---------------- err[b,t,s] = || preds[b,t-1,s,:] - h[b,t,:] || ----------------
__global__ void err_kernel(const float* __restrict__ h)
{
    int gw = (blockIdx.x * blockDim.x + threadIdx.x) >> 5;
    int lane = threadIdx.x & 31;
    if (gw >= Mtot * Sn) return;
    int s = gw & 3, m = gw >> 2;
    int t = m & (Tn - 1);
    if (t == 0) { if (!lane) g_err[m*Sn + s] = 0.f; return; }
    const float* p  = g_preds + ((size_t)s*Mtot + m - 1) * Dm;
    const float* hh = h + (size_t)m * Dm;
    float acc = 0.f;
    #pragma unroll 4
    for (int d = lane; d < Dm; d += 32) { float df = p[d] - hh[d]; acc += df*df; }
    #pragma unroll
    for (int o = 16; o; o >>= 1) acc += __shfl_down_sync(0xffffffffu, acc, o);
    if (!lane) g_err[m*Sn + s] = sqrtf(acc + 1e-8f);
}

__global__ void errmean_kernel()
{
    int i = blockIdx.x * blockDim.x + threadIdx.x;
    if (i >= Tn * Sn) return;
    int s = i & 3, t = i >> 2;
    float acc = 0.f;
    #pragma unroll
    for (int b = 0; b < Bb; b++) acc += g_err[((size_t)(b*Tn + t))*Sn + s];
    g_a[i] = acc * 0.125f;
}

__global__ void scan_mu_kernel()
{
    __shared__ float sm[Tn*Sn];
    for (int i = threadIdx.x; i < Tn*Sn; i += blockDim.x) sm[i] = g_a[i];
    __syncthreads();
    if (threadIdx.x < Sn) {
        int s = threadIdx.x;
        float mu = 0.f;
        for (int t = 0; t < Tn; t++) {
            g_mu[t*Sn + s] = mu;
            if (t > 0) mu = 0.99f*mu + 0.01f*sm[t*Sn + s];
        }
    }
}

__global__ void mad_kernel()
{
    int i = blockIdx.x * blockDim.x + threadIdx.x;
    if (i >= Tn * Sn) return;
    int s = i & 3, t = i >> 2;
    float mu = g_mu[i];
    float acc = 0.f;
    #pragma unroll
    for (int b = 0; b < Bb; b++) acc += fabsf(g_err[((size_t)(b*Tn + t))*Sn + s] - mu);
    g_mad[i] = acc * 0.125f;
}

__global__ void scan_sigma_kernel()
{
    __shared__ float sm[Tn*Sn];
    for (int i = threadIdx.x; i < Tn*Sn; i += blockDim.x) sm[i] = g_mad[i];
    __syncthreads();
    if (threadIdx.x < Sn) {
        int s = threadIdx.x;
        float sg = 1.f;
        for (int t = 0; t < Tn; t++) {
            g_sig[t*Sn + s] = sg;
            if (t > 0) sg = 0.99f*sg + 0.01f*sm[t*Sn + s];
        }
    }
}

__global__ void z_kernel()
{
    int i = blockIdx.x * blockDim.x + threadIdx.x;
    if (i >= Mtot * Sn) return;
    int s = i & 3, m = i >> 2;
    int t = m & (Tn - 1);
    g_z[i] = (t == 0) ? 0.f
                      : (g_err[i] - g_mu[t*Sn + s]) / fmaxf(g_sig[t*Sn + s], 1e-3f);
}

// ---------------- gate for all 3 hypothetical states ----------------
__global__ void gate3_kernel(const float* __restrict__ gate_W1, const float* __restrict__ gate_W2,
                             const float* __restrict__ gate_b2, const float* __restrict__ se)
{
    int gw = (blockIdx.x * blockDim.x + threadIdx.x) >> 5;
    int lane = threadIdx.x & 31;
    if (gw >= Mtot * Sn) return;
    int s = gw & 3, m = gw >> 2;
    const float* W1 = gate_W1 + (size_t)s * 521 * GH;
    const float* hb = g_hgate + ((size_t)s*Mtot + m) * GH;
    float zz = g_z[m*Sn + s];
    float base0 = hb[lane]      + zz * W1[512*GH + lane];
    float base1 = hb[lane + 32] + zz * W1[512*GH + lane + 32];
    float se0[3] = {0,0,0}, se1[3] = {0,0,0};
    #pragma unroll
    for (int e = 0; e < 8; e++) {
        float wa = W1[(513+e)*GH + lane];
        float wb = W1[(513+e)*GH + lane + 32];
        #pragma unroll
        for (int st = 0; st < 3; st++) {
            float sv = se[st*8 + e];
            se0[st] += sv * wa; se1[st] += sv * wb;
        }
    }
    float w20 = gate_W2[s*GH + lane], w21 = gate_W2[s*GH + lane + 32];
    float b2 = gate_b2[s];
    #pragma unroll
    for (int st = 0; st < 3; st++) {
        float v = fmaxf(base0 + se0[st], 0.f)*w20 + fmaxf(base1 + se1[st], 0.f)*w21;
        #pragma unroll
        for (int o = 16; o; o >>= 1) v += __shfl_down_sync(0xffffffffu, v, o);
        if (!lane) g_g3[((size_t)m*Sn + s)*3 + st] = 1.f / (1.f + expf(-(v + b2)));
    }
}

__global__ void g3mean_kernel()
{
    int i = blockIdx.x * blockDim.x + threadIdx.x;
    if (i >= Tn*Sn*3) return;
    int st = i % 3, r = i / 3;
    int s = r & 3, t = r >> 2;
    float acc = 0.f;
    #pragma unroll
    for (int b = 0; b < Bb; b++)
        acc += g_g3[(((size_t)b*Tn + t)*Sn + s)*3 + st];
    g_g3m[i] = acc * 0.125f;
}

__global__ void state_scan_kernel()
{
    __shared__ float sm[12288];
    float ema = 0.5f; int cur = 0;
    for (int ph = 0; ph < 2; ph++) {
        __syncthreads();
        for (int i = threadIdx.x; i < 12288; i += blockDim.x) sm[i] = g_g3m[ph*12288 + i];
        __syncthreads();
        if (threadIdx.x < Sn) {
            int s = threadIdx.x;
            for (int tt = 0; tt < 1024; tt++) {
                int t = ph*1024 + tt;
                g_state[t*Sn + s] = cur;
                float gm = sm[(tt*Sn + s)*3 + cur];
                ema = 0.99f*ema + 0.01f*gm;
                if (cur == 0)      { if (ema < 0.1f)  cur = 1; }
                else if (cur == 1) { if (ema < 0.03f) cur = 2; else if (ema > 0.25f) cur = 0; }
                else               { if (ema > 0.25f) cur = 0; }
            }
        }
    }
}

__global__ void geff_kernel()
{
    int i = blockIdx.x * blockDim.x + threadIdx.x;
    if (i >= Mtot * Sn) return;
    int s = i & 3, m = i >> 2;
    int t = m & (Tn - 1);
    int st = g_state[t*Sn + s];
    float gn = (st == 0) ? 1.0f : ((st == 1) ? 0.5f : 0.1f);
    g_geff[i] = g_g3[(size_t)i*3 + st] * gn;
}

// ---------------- m recurrence ----------------
__global__ void mscan_kernel(const float* __restrict__ w0, float* __restrict__ out)
{
    int blk = blockIdx.x;
    int q = blk & 3;
    int bs = blk >> 2;
    int s = bs & 3, b = bs >> 2;
    int lane = threadIdx.x;
    int d4 = q*32 + lane;

    const float4* wp = (const float4*)g_wenc + ((size_t)s*Mtot + (size_t)b*Tn)*(Dm/4) + d4;
    float4* op = (float4*)out + ((size_t)b*Tn)*(Sn*Dm/4) + s*(Dm/4) + d4;
    const float* gp = g_geff + ((size_t)b*Tn)*Sn + s;

    float4 m = ((const float4*)w0)[s*(Dm/4) + d4];
    #pragma unroll 4
    for (int t = 0; t < Tn; t++) {
        float ge = __ldg(gp + (size_t)t*Sn);
        float4 w = __ldg(wp + (size_t)t*(Dm/4));
        float om = 1.f - ge;
        m.x = om*m.x + ge*w.x;
        m.y = om*m.y + ge*w.y;
        m.z = om*m.z + ge*w.z;
        m.w = om*m.w + ge*w.w;
        op[(size_t)t*(Sn*Dm/4)] = m;
    }
}

// ---------------- launch ----------------
extern "C" void kernel_launch(void* const* d_in, const int* in_sizes, int n_in,
                              void* d_out, int out_size)
{
    const float* h        = (const float*)d_in[0];
    const float* pred_W   = (const float*)d_in[1];
    const float* pred_b   = (const float*)d_in[2];
    const float* gate_W1  = (const float*)d_in[3];
    const float* gate_b1  = (const float*)d_in[4];
    const float* gate_W2  = (const float*)d_in[5];
    const float* gate_b2  = (const float*)d_in[6];
    const float* write_W  = (const float*)d_in[7];
    const float* write_b  = (const float*)d_in[8];
    const float* w0       = (const float*)d_in[9];
    const float* st_embed = (const float*)d_in[10];
    float* out = (float*)d_out;

    const int smem0 = 2*ATILE_B + 2*(128*ROWB);   // 73728
    const int smem1 = 2*ATILE_B + 2*(64*ROWB);    // 55296
    static bool attr_done = false;
    if (!attr_done) {
        cudaFuncSetAttribute(gemm_mma<0>, cudaFuncAttributeMaxDynamicSharedMemorySize, smem0);
        cudaFuncSetAttribute(gemm_mma<1>, cudaFuncAttributeMaxDynamicSharedMemorySize, smem1);
        attr_done = true;
    }

    convA_kernel<<<(Mtot*Dm + 255)/256, 256>>>(h);
    convB_kernel<<<(Sn*NCOMB*Dm + 255)/256, 256>>>(pred_W, write_W, gate_W1);

    gemm_mma<0><<<dim3(8, 128, Sn), 256, smem0>>>(pred_b, write_b, gate_b1);
    gemm_mma<1><<<dim3(1, 128, Sn), 256, smem1>>>(pred_b, write_b, gate_b1);

    err_kernel<<<(Mtot*Sn*32 + 255)/256, 256>>>(h);
    errmean_kernel<<<(Tn*Sn + 255)/256, 256>>>();
    scan_mu_kernel<<<1, 256>>>();
    mad_kernel<<<(Tn*Sn + 255)/256, 256>>>();
    scan_sigma_kernel<<<1, 256>>>();
    z_kernel<<<(Mtot*Sn + 255)/256, 256>>>();

    gate3_kernel<<<(Mtot*Sn*32 + 255)/256, 256>>>(gate_W1, gate_W2, gate_b2, st_embed);
    g3mean_kernel<<<(Tn*Sn*3 + 255)/256, 256>>>();
    state_scan_kernel<<<1, 256>>>();
    geff_kernel<<<(Mtot*Sn + 255)/256, 256>>>();

    mscan_kernel<<<Bb*Sn*4, 32>>>(w0, out);
}

// round 5
// speedup vs baseline: 1.8362x; 1.0095x over previous
#include <cuda_runtime.h>
#include <cuda_bf16.h>
#include <math.h>
#include <stdint.h>

#define Bb   8
#define Tn   2048
#define Dm   512
#define Sn   4
#define GH   64
#define Mtot (Bb*Tn)          // 16384
#define NCOMB 1088            // 512 pred | 512 wenc | 64 gate-hidden
#define KEXT  1024            // 512 hi | 512 lo

// ---------------- scratch (static device globals) ----------------
__device__ __nv_bfloat16 g_Abf[(size_t)Mtot*KEXT];        // [m][k]
__device__ __nv_bfloat16 g_Bbf[(size_t)Sn*NCOMB*KEXT];    // [s][n][k]
__device__ float g_wenc [(size_t)Sn*Mtot*Dm];
__device__ float g_hgate[(size_t)Sn*Mtot*GH];
__device__ float g_errsq[Mtot*Sn];
__device__ float g_err [Mtot*Sn];
__device__ float g_z   [Mtot*Sn];
__device__ float g_a   [Tn*Sn];
__device__ float g_mu  [Tn*Sn];
__device__ float g_mad [Tn*Sn];
__device__ float g_sig [Tn*Sn];
__device__ float g_g3  [(size_t)Mtot*Sn*3];
__device__ float g_g3m [Tn*Sn*3];
__device__ int   g_state[Tn*Sn];
__device__ float g_geff[Mtot*Sn];

// ---------------- prep: fp32 -> bf16 hi/lo split ----------------
__global__ void convA_kernel(const float* __restrict__ h)
{
    int i = blockIdx.x * blockDim.x + threadIdx.x;
    if (i >= Mtot * Dm) return;
    int m = i >> 9, d = i & 511;
    float a = h[i];
    __nv_bfloat16 hi = __float2bfloat16(a);
    float lo = a - __bfloat162float(hi);
    g_Abf[(size_t)m*KEXT + d]       = hi;
    g_Abf[(size_t)m*KEXT + 512 + d] = __float2bfloat16(lo);
}

__global__ void convB_kernel(const float* __restrict__ pred_W, const float* __restrict__ write_W,
                             const float* __restrict__ gate_W1)
{
    int i = blockIdx.x * blockDim.x + threadIdx.x;
    if (i >= Sn * NCOMB * Dm) return;
    int d = i & 511;
    int r = i >> 9;
    int n = r % NCOMB;
    int s = r / NCOMB;
    float v;
    if (n < 512)       v = pred_W [((size_t)s*512 + d)*512 + n];
    else if (n < 1024) v = write_W[((size_t)s*512 + d)*512 + (n - 512)];
    else               v = gate_W1[((size_t)s*521 + d)*64  + (n - 1024)];
    __nv_bfloat16 hi = __float2bfloat16(v);
    float lo = v - __bfloat162float(hi);
    size_t base = ((size_t)s*NCOMB + n) * KEXT;
    g_Bbf[base + d]       = hi;
    g_Bbf[base + 512 + d] = __float2bfloat16(lo);
}

__global__ void zero_errsq_kernel()
{
    int i = blockIdx.x * blockDim.x + threadIdx.x;
    if (i < Mtot*Sn) g_errsq[i] = 0.f;
}

// ================= mma.sync helpers =================
__device__ __forceinline__ uint32_t smem_u32(const void* p) {
    uint32_t a;
    asm("{ .reg .u64 t; cvta.to.shared.u64 t, %1; cvt.u32.u64 %0, t; }" : "=r"(a) : "l"(p));
    return a;
}
#define CP16(dst, src) asm volatile("cp.async.cg.shared.global [%0], [%1], 16;" :: "r"(dst), "l"(src))
#define CP_COMMIT()    asm volatile("cp.async.commit_group;" ::: "memory")
#define CP_WAIT1()     asm volatile("cp.async.wait_group 1;" ::: "memory")
#define LDSM4(r0,r1,r2,r3,addr) \
    asm volatile("ldmatrix.sync.aligned.m8n8.x4.shared.b16 {%0,%1,%2,%3}, [%4];" \
        : "=r"(r0),"=r"(r1),"=r"(r2),"=r"(r3) : "r"(addr))
#define MMA16816(d, a, b) \
    asm volatile("mma.sync.aligned.m16n8k16.row.col.f32.bf16.bf16.f32 " \
        "{%0,%1,%2,%3},{%4,%5,%6,%7},{%8,%9},{%0,%1,%2,%3};" \
        : "+f"((d)[0]),"+f"((d)[1]),"+f"((d)[2]),"+f"((d)[3]) \
        : "r"((a)[0]),"r"((a)[1]),"r"((a)[2]),"r"((a)[3]), "r"((b)[0]),"r"((b)[1]))

// smem tile: k-tile 64, pitch 72 bf16 (144B) per row -> conflict-free ldmatrix
#define PITCH    72
#define ROWB     (PITCH*2)          // 144 bytes per row
#define ATILE_B  (128*ROWB)         // 18432 bytes
#define STAGES   3
#define NT       24

// CFG 0: big GEMM (N-tile 128, warp tile 64x32, MA=4); which==0 fuses err reduction
// CFG 1: gate GEMM (N=64, warp tile 32x32, MA=2)
template<int CFG>
__global__ void __launch_bounds__(256, 2)
gemm_mma(const float* __restrict__ pred_b, const float* __restrict__ write_b,
         const float* __restrict__ gate_b1, const float* __restrict__ hseq)
{
    constexpr int MA = CFG ? 2 : 4;
    constexpr int BROWS = CFG ? 64 : 128;
    constexpr int BTILE_B = BROWS * ROWB;
    extern __shared__ __align__(16) char smem[];
    const uint32_t sAu = smem_u32(smem);
    const uint32_t sBu = sAu + STAGES*ATILE_B;

    const int tid = threadIdx.x;
    const int wid = tid >> 5, lane = tid & 31;
    const int s = blockIdx.z;
    const int mbase = blockIdx.y * 128;

    int which, nbase, colbase;
    if (CFG == 0) {
        which = blockIdx.x >> 2;                 // 0: preds, 1: wenc
        int nt = blockIdx.x & 3;
        nbase = which * 512 + nt * 128;
        colbase = nt * 128;
    } else {
        which = 2; nbase = 1024; colbase = 0;
    }

    int mw, nw;
    if (CFG == 0) { mw = wid >> 2; nw = wid & 3; }
    else          { mw = wid >> 1; nw = wid & 1; }
    const int m0 = mw * (MA*16);
    const int n0 = nw * 32;

    const int idx = lane & 7, sel = lane >> 3;
    const uint32_t aAddrBase = sAu + (uint32_t)(m0 + (sel&1)*8 + idx) * ROWB + (uint32_t)((sel>>1)*8)*2;
    const uint32_t bAddrBase = sBu + (uint32_t)(n0 + (sel>>1)*8 + idx) * ROWB + (uint32_t)((sel&1)*8)*2;

    float acc[MA][4][4];
    #pragma unroll
    for (int i = 0; i < MA; i++)
        #pragma unroll
        for (int j = 0; j < 4; j++)
            #pragma unroll
            for (int q = 0; q < 4; q++) acc[i][j][q] = 0.f;

    const char* Aall = (const char*)g_Abf;
    const char* Ball = (const char*)g_Bbf;

    // chunk c in [0,24): pass p = c>>3, k offset (c&7)*64
    auto load_tile = [&](int c, int slot) {
        const int p = c >> 3, kk = (c & 7) * 64;
        const int acol = ((p == 2) ? 512 : 0) + kk;
        const int bcol = ((p == 1) ? 512 : 0) + kk;
        const uint32_t ab = sAu + slot * ATILE_B;
        const uint32_t bb = sBu + slot * BTILE_B;
        #pragma unroll
        for (int it = 0; it < 4; it++) {
            int g = tid + it*256;                 // 1024 granules: row*8 + gc
            int row = g >> 3, gc = g & 7;
            CP16(ab + row*ROWB + gc*16,
                 Aall + ((size_t)(mbase + row)*KEXT + acol + gc*8)*2);
        }
        #pragma unroll
        for (int it = 0; it < BROWS/32; it++) {
            int g = tid + it*256;
            int row = g >> 3, gc = g & 7;
            CP16(bb + row*ROWB + gc*16,
                 Ball + (((size_t)s*NCOMB + nbase + row)*KEXT + bcol + gc*8)*2);
        }
        CP_COMMIT();
    };

    load_tile(0, 0);
    load_tile(1, 1);
    int slot = 0;
    for (int c = 0; c < NT; c++) {
        CP_WAIT1();            // stage c resident (<=1 group outstanding)
        __syncthreads();       // all warps done with slot being overwritten + data visible
        if (c + 2 < NT) load_tile(c + 2, (c + 2) % STAGES);
        else CP_COMMIT();
        const uint32_t aOff = aAddrBase + slot*ATILE_B;
        const uint32_t bOff = bAddrBase + slot*BTILE_B;
        #pragma unroll
        for (int ks = 0; ks < 4; ks++) {
            uint32_t afr[MA][4], bfr[4][2];
            #pragma unroll
            for (int i = 0; i < MA; i++)
                LDSM4(afr[i][0], afr[i][1], afr[i][2], afr[i][3],
                      aOff + i*16*ROWB + ks*32);
            #pragma unroll
            for (int jp = 0; jp < 2; jp++) {
                uint32_t r0, r1, r2, r3;
                LDSM4(r0, r1, r2, r3, bOff + jp*16*ROWB + ks*32);
                bfr[jp*2+0][0] = r0; bfr[jp*2+0][1] = r1;
                bfr[jp*2+1][0] = r2; bfr[jp*2+1][1] = r3;
            }
            #pragma unroll
            for (int i = 0; i < MA; i++)
                #pragma unroll
                for (int j = 0; j < 4; j++)
                    MMA16816(acc[i][j], afr[i], bfr[j]);
        }
        slot = (slot + 1 == STAGES) ? 0 : slot + 1;
    }

    // ---------------- epilogue ----------------
    const int rbase = mbase + m0 + (lane >> 2);
    const int cbase = colbase + n0 + (lane & 3) * 2;

    if (which == 0) {
        // fused err: sum (pred - h[r+1])^2 over this CTA's 128 cols, atomic into g_errsq
        const float* bias = pred_b + s*Dm;
        float rowsum[MA][2];
        #pragma unroll
        for (int i = 0; i < MA; i++) { rowsum[i][0] = 0.f; rowsum[i][1] = 0.f; }
        #pragma unroll
        for (int j = 0; j < 4; j++) {
            const int col = cbase + j*8;
            const float b0 = __ldg(bias + col), b1 = __ldg(bias + col + 1);
            #pragma unroll
            for (int i = 0; i < MA; i++) {
                const int r1 = rbase + i*16, r2 = r1 + 8;
                float2 h1 = *(const float2*)(hseq + (size_t)(r1+1)*Dm + col);
                float2 h2 = *(const float2*)(hseq + (size_t)(r2+1)*Dm + col);
                float d0 = acc[i][j][0] + b0 - h1.x;
                float d1 = acc[i][j][1] + b1 - h1.y;
                float d2 = acc[i][j][2] + b0 - h2.x;
                float d3 = acc[i][j][3] + b1 - h2.y;
                rowsum[i][0] += d0*d0 + d1*d1;
                rowsum[i][1] += d2*d2 + d3*d3;
            }
        }
        #pragma unroll
        for (int i = 0; i < MA; i++) {
            #pragma unroll
            for (int hh = 0; hh < 2; hh++) {
                float v = rowsum[i][hh];
                v += __shfl_xor_sync(0xffffffffu, v, 1);
                v += __shfl_xor_sync(0xffffffffu, v, 2);
                if ((lane & 3) == 0) {
                    int r = rbase + i*16 + hh*8;
                    if ((r & (Tn - 1)) != Tn - 1)
                        atomicAdd(&g_errsq[(r + 1)*Sn + s], v);
                }
            }
        }
        return;
    }

    float* Cm; const float* bias; int stride;
    if (which == 1) { Cm = g_wenc + (size_t)s*Mtot*Dm; bias = write_b + s*Dm; stride = Dm; }
    else            { Cm = g_hgate + (size_t)s*Mtot*GH; bias = gate_b1 + s*GH; stride = GH; }

    #pragma unroll
    for (int j = 0; j < 4; j++) {
        const int col = cbase + j*8;
        const float b0 = __ldg(bias + col), b1 = __ldg(bias + col + 1);
        #pragma unroll
        for (int i = 0; i < MA; i++) {
            const int r = rbase + i*16;
            float2 o0 = { acc[i][j][0] + b0, acc[i][j][1] + b1 };
            float2 o1 = { acc[i][j][2] + b0, acc[i][j][3] + b1 };
            *(float2*)(Cm + (size_t)r*stride + col)       = o0;
            *(float2*)(Cm + (size_t)(r+8)*stride + col)   = o1;
        }
    }
}

// ---------------- err finalize: sqrt(sum + 1e-8), 0 at t=0 ----------------
__global__ void err_finalize_kernel()
{
    int i = blockIdx.x * blockDim.x + threadIdx.x;
    if (i >= Mtot * Sn) return;
    int t = (i >> 2) & (Tn - 1);
    g_err[i] = (t == 0) ? 0.f : sqrtf(g_errsq[i] + 1e-8f);
}

__global__ void errmean_kernel()
{
    int i = blockIdx.x * blockDim.x + threadIdx.x;
    if (i >= Tn * Sn) return;
    int s = i & 3, t = i >> 2;
    float acc = 0.f;
    #pragma unroll
    for (int b = 0; b < Bb; b++) acc += g_err[((size_t)(b*Tn + t))*Sn + s];
    g_a[i] = acc * 0.125f;
}

__global__ void scan_mu_kernel()
{
    __shared__ float sm[Tn*Sn];
    for (int i = threadIdx.x; i < Tn*Sn; i += blockDim.x) sm[i] = g_a[i];
    __syncthreads();
    if (threadIdx.x < Sn) {
        int s = threadIdx.x;
        float mu = 0.f;
        for (int t = 0; t < Tn; t++) {
            g_mu[t*Sn + s] = mu;
            if (t > 0) mu = 0.99f*mu + 0.01f*sm[t*Sn + s];
        }
    }
}

__global__ void mad_kernel()
{
    int i = blockIdx.x * blockDim.x + threadIdx.x;
    if (i >= Tn * Sn) return;
    int s = i & 3, t = i >> 2;
    float mu = g_mu[i];
    float acc = 0.f;
    #pragma unroll
    for (int b = 0; b < Bb; b++) acc += fabsf(g_err[((size_t)(b*Tn + t))*Sn + s] - mu);
    g_mad[i] = acc * 0.125f;
}

__global__ void scan_sigma_kernel()
{
    __shared__ float sm[Tn*Sn];
    for (int i = threadIdx.x; i < Tn*Sn; i += blockDim.x) sm[i] = g_mad[i];
    __syncthreads();
    if (threadIdx.x < Sn) {
        int s = threadIdx.x;
        float sg = 1.f;
        for (int t = 0; t < Tn; t++) {
            g_sig[t*Sn + s] = sg;
            if (t > 0) sg = 0.99f*sg + 0.01f*sm[t*Sn + s];
        }
    }
}

__global__ void z_kernel()
{
    int i = blockIdx.x * blockDim.x + threadIdx.x;
    if (i >= Mtot * Sn) return;
    int s = i & 3, m = i >> 2;
    int t = m & (Tn - 1);
    g_z[i] = (t == 0) ? 0.f
                      : (g_err[i] - g_mu[t*Sn + s]) / fmaxf(g_sig[t*Sn + s], 1e-3f);
}

// ---------------- gate for all 3 hypothetical states ----------------
__global__ void gate3_kernel(const float* __restrict__ gate_W1, const float* __restrict__ gate_W2,
                             const float* __restrict__ gate_b2, const float* __restrict__ se)
{
    int gw = (blockIdx.x * blockDim.x + threadIdx.x) >> 5;
    int lane = threadIdx.x & 31;
    if (gw >= Mtot * Sn) return;
    int s = gw & 3, m = gw >> 2;
    const float* W1 = gate_W1 + (size_t)s * 521 * GH;
    const float* hb = g_hgate + ((size_t)s*Mtot + m) * GH;
    float zz = g_z[m*Sn + s];
    float base0 = hb[lane]      + zz * W1[512*GH + lane];
    float base1 = hb[lane + 32] + zz * W1[512*GH + lane + 32];
    float se0[3] = {0,0,0}, se1[3] = {0,0,0};
    #pragma unroll
    for (int e = 0; e < 8; e++) {
        float wa = W1[(513+e)*GH + lane];
        float wb = W1[(513+e)*GH + lane + 32];
        #pragma unroll
        for (int st = 0; st < 3; st++) {
            float sv = se[st*8 + e];
            se0[st] += sv * wa; se1[st] += sv * wb;
        }
    }
    float w20 = gate_W2[s*GH + lane], w21 = gate_W2[s*GH + lane + 32];
    float b2 = gate_b2[s];
    #pragma unroll
    for (int st = 0; st < 3; st++) {
        float v = fmaxf(base0 + se0[st], 0.f)*w20 + fmaxf(base1 + se1[st], 0.f)*w21;
        #pragma unroll
        for (int o = 16; o; o >>= 1) v += __shfl_down_sync(0xffffffffu, v, o);
        if (!lane) g_g3[((size_t)m*Sn + s)*3 + st] = 1.f / (1.f + expf(-(v + b2)));
    }
}

__global__ void g3mean_kernel()
{
    int i = blockIdx.x * blockDim.x + threadIdx.x;
    if (i >= Tn*Sn*3) return;
    int st = i % 3, r = i / 3;
    int s = r & 3, t = r >> 2;
    float acc = 0.f;
    #pragma unroll
    for (int b = 0; b < Bb; b++)
        acc += g_g3[(((size_t)b*Tn + t)*Sn + s)*3 + st];
    g_g3m[i] = acc * 0.125f;
}

__global__ void state_scan_kernel()
{
    __shared__ float sm[12288];
    float ema = 0.5f; int cur = 0;
    for (int ph = 0; ph < 2; ph++) {
        __syncthreads();
        for (int i = threadIdx.x; i < 12288; i += blockDim.x) sm[i] = g_g3m[ph*12288 + i];
        __syncthreads();
        if (threadIdx.x < Sn) {
            int s = threadIdx.x;
            for (int tt = 0; tt < 1024; tt++) {
                int t = ph*1024 + tt;
                g_state[t*Sn + s] = cur;
                float gm = sm[(tt*Sn + s)*3 + cur];
                ema = 0.99f*ema + 0.01f*gm;
                if (cur == 0)      { if (ema < 0.1f)  cur = 1; }
                else if (cur == 1) { if (ema < 0.03f) cur = 2; else if (ema > 0.25f) cur = 0; }
                else               { if (ema > 0.25f) cur = 0; }
            }
        }
    }
}

__global__ void geff_kernel()
{
    int i = blockIdx.x * blockDim.x + threadIdx.x;
    if (i >= Mtot * Sn) return;
    int s = i & 3, m = i >> 2;
    int t = m & (Tn - 1);
    int st = g_state[t*Sn + s];
    float gn = (st == 0) ? 1.0f : ((st == 1) ? 0.5f : 0.1f);
    g_geff[i] = g_g3[(size_t)i*3 + st] * gn;
}

// ---------------- m recurrence ----------------
__global__ void mscan_kernel(const float* __restrict__ w0, float* __restrict__ out)
{
    int blk = blockIdx.x;
    int q = blk & 3;
    int bs = blk >> 2;
    int s = bs & 3, b = bs >> 2;
    int lane = threadIdx.x;
    int d4 = q*32 + lane;

    const float4* wp = (const float4*)g_wenc + ((size_t)s*Mtot + (size_t)b*Tn)*(Dm/4) + d4;
    float4* op = (float4*)out + ((size_t)b*Tn)*(Sn*Dm/4) + s*(Dm/4) + d4;
    const float* gp = g_geff + ((size_t)b*Tn)*Sn + s;

    float4 m = ((const float4*)w0)[s*(Dm/4) + d4];
    #pragma unroll 4
    for (int t = 0; t < Tn; t++) {
        float ge = __ldg(gp + (size_t)t*Sn);
        float4 w = __ldg(wp + (size_t)t*(Dm/4));
        float om = 1.f - ge;
        m.x = om*m.x + ge*w.x;
        m.y = om*m.y + ge*w.y;
        m.z = om*m.z + ge*w.z;
        m.w = om*m.w + ge*w.w;
        op[(size_t)t*(Sn*Dm/4)] = m;
    }
}

// ---------------- launch ----------------
extern "C" void kernel_launch(void* const* d_in, const int* in_sizes, int n_in,
                              void* d_out, int out_size)
{
    const float* h        = (const float*)d_in[0];
    const float* pred_b   = (const float*)d_in[2];
    const float* pred_W   = (const float*)d_in[1];
    const float* gate_W1  = (const float*)d_in[3];
    const float* gate_b1  = (const float*)d_in[4];
    const float* gate_W2  = (const float*)d_in[5];
    const float* gate_b2  = (const float*)d_in[6];
    const float* write_W  = (const float*)d_in[7];
    const float* write_b  = (const float*)d_in[8];
    const float* w0       = (const float*)d_in[9];
    const float* st_embed = (const float*)d_in[10];
    float* out = (float*)d_out;

    const int smem0 = STAGES*(ATILE_B + 128*ROWB);   // 110592
    const int smem1 = STAGES*(ATILE_B + 64*ROWB);    // 82944
    static bool attr_done = false;
    if (!attr_done) {
        cudaFuncSetAttribute(gemm_mma<0>, cudaFuncAttributeMaxDynamicSharedMemorySize, smem0);
        cudaFuncSetAttribute(gemm_mma<1>, cudaFuncAttributeMaxDynamicSharedMemorySize, smem1);
        attr_done = true;
    }

    convA_kernel<<<(Mtot*Dm + 255)/256, 256>>>(h);
    convB_kernel<<<(Sn*NCOMB*Dm + 255)/256, 256>>>(pred_W, write_W, gate_W1);
    zero_errsq_kernel<<<(Mtot*Sn + 255)/256, 256>>>();

    gemm_mma<0><<<dim3(8, 128, Sn), 256, smem0>>>(pred_b, write_b, gate_b1, h);
    gemm_mma<1><<<dim3(1, 128, Sn), 256, smem1>>>(pred_b, write_b, gate_b1, h);

    err_finalize_kernel<<<(Mtot*Sn + 255)/256, 256>>>();
    errmean_kernel<<<(Tn*Sn + 255)/256, 256>>>();
    scan_mu_kernel<<<1, 256>>>();
    mad_kernel<<<(Tn*Sn + 255)/256, 256>>>();
    scan_sigma_kernel<<<1, 256>>>();
    z_kernel<<<(Mtot*Sn + 255)/256, 256>>>();

    gate3_kernel<<<(Mtot*Sn*32 + 255)/256, 256>>>(gate_W1, gate_W2, gate_b2, st_embed);
    g3mean_kernel<<<(Tn*Sn*3 + 255)/256, 256>>>();
    state_scan_kernel<<<1, 256>>>();
    geff_kernel<<<(Mtot*Sn + 255)/256, 256>>>();

    mscan_kernel<<<Bb*Sn*4, 32>>>(w0, out);
}

// round 6
// speedup vs baseline: 2.8822x; 1.5697x over previous
#include <cuda_runtime.h>
#include <cuda_fp16.h>
#include <math.h>
#include <stdint.h>

#define Bb   8
#define Tn   2048
#define Dm   512
#define Sn   4
#define GH   64
#define Mtot (Bb*Tn)          // 16384
#define NCOMB 1088            // 512 pred | 512 wenc | 64 gate-hidden
#define KEXT  1024            // 512 hi | 512 lo

// ---------------- scratch (static device globals) ----------------
__device__ __half g_Ahf[(size_t)Mtot*KEXT];        // [m][k]
__device__ __half g_Bhf[(size_t)Sn*NCOMB*KEXT];    // [s][n][k]
__device__ float g_wenc [(size_t)Sn*Mtot*Dm];
__device__ float g_hgate[(size_t)Sn*Mtot*GH];
__device__ float g_errsq[Mtot*Sn];
__device__ float g_err [Mtot*Sn];
__device__ float g_z   [Mtot*Sn];
__device__ float g_a   [Tn*Sn];
__device__ float g_mu  [Tn*Sn];
__device__ float g_mad [Tn*Sn];
__device__ float g_sig [Tn*Sn];
__device__ float g_g3  [(size_t)Mtot*Sn*3];
__device__ float g_g3m [Tn*Sn*3];
__device__ int   g_state[Tn*Sn];
__device__ float g_geff[Mtot*Sn];

// ---------------- prep: fp32 -> fp16 hi/lo split ----------------
__global__ void convA_kernel(const float* __restrict__ h)
{
    int i = blockIdx.x * blockDim.x + threadIdx.x;
    if (i >= Mtot * Dm) return;
    int m = i >> 9, d = i & 511;
    float a = h[i];
    __half hi = __float2half(a);
    float lo = a - __half2float(hi);
    g_Ahf[(size_t)m*KEXT + d]       = hi;
    g_Ahf[(size_t)m*KEXT + 512 + d] = __float2half(lo);
}

// transpose [d][n] -> [n][d] via 32x33 smem tile; both sides coalesced
__global__ void convB_kernel(const float* __restrict__ pred_W, const float* __restrict__ write_W,
                             const float* __restrict__ gate_W1)
{
    __shared__ float tile[32][33];
    const int s = blockIdx.z;
    const int n0 = blockIdx.y * 32;      // 0..1087
    const int d0 = blockIdx.x * 32;      // 0..511
    const int tx = threadIdx.x, ty = threadIdx.y;   // 32 x 8

    const float* src; int strideN, ncol;
    if (n0 < 512)       { src = pred_W  + (size_t)s*512*512; strideN = 512; ncol = n0 + tx; }
    else if (n0 < 1024) { src = write_W + (size_t)s*512*512; strideN = 512; ncol = n0 - 512 + tx; }
    else                { src = gate_W1 + (size_t)s*521*64;  strideN = 64;  ncol = n0 - 1024 + tx; }

    #pragma unroll
    for (int i = 0; i < 4; i++)
        tile[ty + 8*i][tx] = src[(size_t)(d0 + ty + 8*i)*strideN + ncol];
    __syncthreads();
    #pragma unroll
    for (int i = 0; i < 4; i++) {
        float v = tile[tx][ty + 8*i];
        __half hi = __float2half(v);
        __half lo = __float2half(v - __half2float(hi));
        size_t base = ((size_t)s*NCOMB + n0 + ty + 8*i)*KEXT + d0 + tx;
        g_Bhf[base]       = hi;
        g_Bhf[base + 512] = lo;
    }
}

__global__ void zero_errsq_kernel()
{
    int i = blockIdx.x * blockDim.x + threadIdx.x;
    if (i < Mtot*Sn) g_errsq[i] = 0.f;
}

// ================= mma.sync helpers =================
__device__ __forceinline__ uint32_t smem_u32(const void* p) {
    uint32_t a;
    asm("{ .reg .u64 t; cvta.to.shared.u64 t, %1; cvt.u32.u64 %0, t; }" : "=r"(a) : "l"(p));
    return a;
}
#define CP16(dst, src) asm volatile("cp.async.cg.shared.global [%0], [%1], 16;" :: "r"(dst), "l"(src))
#define CP_COMMIT()    asm volatile("cp.async.commit_group;" ::: "memory")
#define CP_WAIT1()     asm volatile("cp.async.wait_group 1;" ::: "memory")
#define LDSM4(r0,r1,r2,r3,addr) \
    asm volatile("ldmatrix.sync.aligned.m8n8.x4.shared.b16 {%0,%1,%2,%3}, [%4];" \
        : "=r"(r0),"=r"(r1),"=r"(r2),"=r"(r3) : "r"(addr))
#define MMA16816(d, a, b) \
    asm volatile("mma.sync.aligned.m16n8k16.row.col.f32.f16.f16.f32 " \
        "{%0,%1,%2,%3},{%4,%5,%6,%7},{%8,%9},{%0,%1,%2,%3};" \
        : "+f"((d)[0]),"+f"((d)[1]),"+f"((d)[2]),"+f"((d)[3]) \
        : "r"((a)[0]),"r"((a)[1]),"r"((a)[2]),"r"((a)[3]), "r"((b)[0]),"r"((b)[1]))

// smem tile: k-tile 64, pitch 72 fp16 (144B) per row -> conflict-free ldmatrix
#define PITCH    72
#define ROWB     (PITCH*2)          // 144 bytes per row
#define ATILE_B  (128*ROWB)         // 18432 bytes
#define STAGES   3

// CFG 0: big GEMM; which==0 preds (1-pass, fused err), which==1 wenc (3-pass)
// CFG 1: gate GEMM (N=64, 3-pass)
template<int CFG>
__global__ void __launch_bounds__(256, 2)
gemm_mma(const float* __restrict__ pred_b, const float* __restrict__ write_b,
         const float* __restrict__ gate_b1, const float* __restrict__ hseq)
{
    constexpr int MA = CFG ? 2 : 4;
    constexpr int BROWS = CFG ? 64 : 128;
    constexpr int BTILE_B = BROWS * ROWB;
    extern __shared__ __align__(16) char smem[];
    const uint32_t sAu = smem_u32(smem);
    const uint32_t sBu = sAu + STAGES*ATILE_B;

    const int tid = threadIdx.x;
    const int wid = tid >> 5, lane = tid & 31;
    const int s = blockIdx.z;
    const int mbase = blockIdx.y * 128;

    int which, nbase, colbase, NTloc;
    if (CFG == 0) {
        which = blockIdx.x >> 2;                 // 0: preds, 1: wenc
        int nt = blockIdx.x & 3;
        nbase = which * 512 + nt * 128;
        colbase = nt * 128;
        NTloc = (which == 0) ? 8 : 24;           // preds single-pass
    } else {
        which = 2; nbase = 1024; colbase = 0; NTloc = 24;
    }

    int mw, nw;
    if (CFG == 0) { mw = wid >> 2; nw = wid & 3; }
    else          { mw = wid >> 1; nw = wid & 1; }
    const int m0 = mw * (MA*16);
    const int n0 = nw * 32;

    const int idx = lane & 7, sel = lane >> 3;
    const uint32_t aAddrBase = sAu + (uint32_t)(m0 + (sel&1)*8 + idx) * ROWB + (uint32_t)((sel>>1)*8)*2;
    const uint32_t bAddrBase = sBu + (uint32_t)(n0 + (sel>>1)*8 + idx) * ROWB + (uint32_t)((sel&1)*8)*2;

    float acc[MA][4][4];
    #pragma unroll
    for (int i = 0; i < MA; i++)
        #pragma unroll
        for (int j = 0; j < 4; j++)
            #pragma unroll
            for (int q = 0; q < 4; q++) acc[i][j][q] = 0.f;

    const char* Aall = (const char*)g_Ahf;
    const char* Ball = (const char*)g_Bhf;

    // chunk c: pass p = c>>3 (preds: always 0 since c<8), k offset (c&7)*64
    auto load_tile = [&](int c, int slot) {
        const int p = c >> 3, kk = (c & 7) * 64;
        const int acol = ((p == 2) ? 512 : 0) + kk;
        const int bcol = ((p == 1) ? 512 : 0) + kk;
        const uint32_t ab = sAu + slot * ATILE_B;
        const uint32_t bb = sBu + slot * BTILE_B;
        #pragma unroll
        for (int it = 0; it < 4; it++) {
            int g = tid + it*256;                 // 1024 granules: row*8 + gc
            int row = g >> 3, gc = g & 7;
            CP16(ab + row*ROWB + gc*16,
                 Aall + ((size_t)(mbase + row)*KEXT + acol + gc*8)*2);
        }
        #pragma unroll
        for (int it = 0; it < BROWS/32; it++) {
            int g = tid + it*256;
            int row = g >> 3, gc = g & 7;
            CP16(bb + row*ROWB + gc*16,
                 Ball + (((size_t)s*NCOMB + nbase + row)*KEXT + bcol + gc*8)*2);
        }
        CP_COMMIT();
    };

    load_tile(0, 0);
    load_tile(1, 1);
    int slot = 0;
    for (int c = 0; c < NTloc; c++) {
        CP_WAIT1();
        __syncthreads();
        if (c + 2 < NTloc) load_tile(c + 2, (c + 2) % STAGES);
        else CP_COMMIT();
        const uint32_t aOff = aAddrBase + slot*ATILE_B;
        const uint32_t bOff = bAddrBase + slot*BTILE_B;
        #pragma unroll
        for (int ks = 0; ks < 4; ks++) {
            uint32_t afr[MA][4], bfr[4][2];
            #pragma unroll
            for (int i = 0; i < MA; i++)
                LDSM4(afr[i][0], afr[i][1], afr[i][2], afr[i][3],
                      aOff + i*16*ROWB + ks*32);
            #pragma unroll
            for (int jp = 0; jp < 2; jp++) {
                uint32_t r0, r1, r2, r3;
                LDSM4(r0, r1, r2, r3, bOff + jp*16*ROWB + ks*32);
                bfr[jp*2+0][0] = r0; bfr[jp*2+0][1] = r1;
                bfr[jp*2+1][0] = r2; bfr[jp*2+1][1] = r3;
            }
            #pragma unroll
            for (int i = 0; i < MA; i++)
                #pragma unroll
                for (int j = 0; j < 4; j++)
                    MMA16816(acc[i][j], afr[i], bfr[j]);
        }
        slot = (slot + 1 == STAGES) ? 0 : slot + 1;
    }

    // ---------------- epilogue ----------------
    const int rbase = mbase + m0 + (lane >> 2);
    const int cbase = colbase + n0 + (lane & 3) * 2;

    if (which == 0) {
        // fused err: sum (pred - h[r+1])^2 over this CTA's 128 cols, atomic into g_errsq
        const float* bias = pred_b + s*Dm;
        float rowsum[MA][2];
        #pragma unroll
        for (int i = 0; i < MA; i++) { rowsum[i][0] = 0.f; rowsum[i][1] = 0.f; }
        #pragma unroll
        for (int j = 0; j < 4; j++) {
            const int col = cbase + j*8;
            const float b0 = __ldg(bias + col), b1 = __ldg(bias + col + 1);
            #pragma unroll
            for (int i = 0; i < MA; i++) {
                const int r1 = rbase + i*16, r2 = r1 + 8;
                float2 h1 = *(const float2*)(hseq + (size_t)(r1+1)*Dm + col);
                float2 h2 = *(const float2*)(hseq + (size_t)(r2+1)*Dm + col);
                float d0 = acc[i][j][0] + b0 - h1.x;
                float d1 = acc[i][j][1] + b1 - h1.y;
                float d2 = acc[i][j][2] + b0 - h2.x;
                float d3 = acc[i][j][3] + b1 - h2.y;
                rowsum[i][0] += d0*d0 + d1*d1;
                rowsum[i][1] += d2*d2 + d3*d3;
            }
        }
        #pragma unroll
        for (int i = 0; i < MA; i++) {
            #pragma unroll
            for (int hh = 0; hh < 2; hh++) {
                float v = rowsum[i][hh];
                v += __shfl_xor_sync(0xffffffffu, v, 1);
                v += __shfl_xor_sync(0xffffffffu, v, 2);
                if ((lane & 3) == 0) {
                    int r = rbase + i*16 + hh*8;
                    if ((r & (Tn - 1)) != Tn - 1)
                        atomicAdd(&g_errsq[(r + 1)*Sn + s], v);
                }
            }
        }
        return;
    }

    float* Cm; const float* bias; int stride;
    if (which == 1) { Cm = g_wenc + (size_t)s*Mtot*Dm; bias = write_b + s*Dm; stride = Dm; }
    else            { Cm = g_hgate + (size_t)s*Mtot*GH; bias = gate_b1 + s*GH; stride = GH; }

    #pragma unroll
    for (int j = 0; j < 4; j++) {
        const int col = cbase + j*8;
        const float b0 = __ldg(bias + col), b1 = __ldg(bias + col + 1);
        #pragma unroll
        for (int i = 0; i < MA; i++) {
            const int r = rbase + i*16;
            float2 o0 = { acc[i][j][0] + b0, acc[i][j][1] + b1 };
            float2 o1 = { acc[i][j][2] + b0, acc[i][j][3] + b1 };
            *(float2*)(Cm + (size_t)r*stride + col)       = o0;
            *(float2*)(Cm + (size_t)(r+8)*stride + col)   = o1;
        }
    }
}

// ---------------- err finalize: sqrt(sum + 1e-8), 0 at t=0 ----------------
__global__ void err_finalize_kernel()
{
    int i = blockIdx.x * blockDim.x + threadIdx.x;
    if (i >= Mtot * Sn) return;
    int t = (i >> 2) & (Tn - 1);
    g_err[i] = (t == 0) ? 0.f : sqrtf(g_errsq[i] + 1e-8f);
}

__global__ void errmean_kernel()
{
    int i = blockIdx.x * blockDim.x + threadIdx.x;
    if (i >= Tn * Sn) return;
    int s = i & 3, t = i >> 2;
    float acc = 0.f;
    #pragma unroll
    for (int b = 0; b < Bb; b++) acc += g_err[((size_t)(b*Tn + t))*Sn + s];
    g_a[i] = acc * 0.125f;
}

__global__ void scan_mu_kernel()
{
    __shared__ float sm[Tn*Sn];
    for (int i = threadIdx.x; i < Tn*Sn; i += blockDim.x) sm[i] = g_a[i];
    __syncthreads();
    if (threadIdx.x < Sn) {
        int s = threadIdx.x;
        float mu = 0.f;
        for (int t = 0; t < Tn; t++) {
            g_mu[t*Sn + s] = mu;
            if (t > 0) mu = 0.99f*mu + 0.01f*sm[t*Sn + s];
        }
    }
}

__global__ void mad_kernel()
{
    int i = blockIdx.x * blockDim.x + threadIdx.x;
    if (i >= Tn * Sn) return;
    int s = i & 3, t = i >> 2;
    float mu = g_mu[i];
    float acc = 0.f;
    #pragma unroll
    for (int b = 0; b < Bb; b++) acc += fabsf(g_err[((size_t)(b*Tn + t))*Sn + s] - mu);
    g_mad[i] = acc * 0.125f;
}

__global__ void scan_sigma_kernel()
{
    __shared__ float sm[Tn*Sn];
    for (int i = threadIdx.x; i < Tn*Sn; i += blockDim.x) sm[i] = g_mad[i];
    __syncthreads();
    if (threadIdx.x < Sn) {
        int s = threadIdx.x;
        float sg = 1.f;
        for (int t = 0; t < Tn; t++) {
            g_sig[t*Sn + s] = sg;
            if (t > 0) sg = 0.99f*sg + 0.01f*sm[t*Sn + s];
        }
    }
}

__global__ void z_kernel()
{
    int i = blockIdx.x * blockDim.x + threadIdx.x;
    if (i >= Mtot * Sn) return;
    int s = i & 3, m = i >> 2;
    int t = m & (Tn - 1);
    g_z[i] = (t == 0) ? 0.f
                      : (g_err[i] - g_mu[t*Sn + s]) / fmaxf(g_sig[t*Sn + s], 1e-3f);
}

// ---------------- gate for all 3 hypothetical states ----------------
__global__ void gate3_kernel(const float* __restrict__ gate_W1, const float* __restrict__ gate_W2,
                             const float* __restrict__ gate_b2, const float* __restrict__ se)
{
    int gw = (blockIdx.x * blockDim.x + threadIdx.x) >> 5;
    int lane = threadIdx.x & 31;
    if (gw >= Mtot * Sn) return;
    int s = gw & 3, m = gw >> 2;
    const float* W1 = gate_W1 + (size_t)s * 521 * GH;
    const float* hb = g_hgate + ((size_t)s*Mtot + m) * GH;
    float zz = g_z[m*Sn + s];
    float base0 = hb[lane]      + zz * W1[512*GH + lane];
    float base1 = hb[lane + 32] + zz * W1[512*GH + lane + 32];
    float se0[3] = {0,0,0}, se1[3] = {0,0,0};
    #pragma unroll
    for (int e = 0; e < 8; e++) {
        float wa = W1[(513+e)*GH + lane];
        float wb = W1[(513+e)*GH + lane + 32];
        #pragma unroll
        for (int st = 0; st < 3; st++) {
            float sv = se[st*8 + e];
            se0[st] += sv * wa; se1[st] += sv * wb;
        }
    }
    float w20 = gate_W2[s*GH + lane], w21 = gate_W2[s*GH + lane + 32];
    float b2 = gate_b2[s];
    #pragma unroll
    for (int st = 0; st < 3; st++) {
        float v = fmaxf(base0 + se0[st], 0.f)*w20 + fmaxf(base1 + se1[st], 0.f)*w21;
        #pragma unroll
        for (int o = 16; o; o >>= 1) v += __shfl_down_sync(0xffffffffu, v, o);
        if (!lane) g_g3[((size_t)m*Sn + s)*3 + st] = 1.f / (1.f + expf(-(v + b2)));
    }
}

__global__ void g3mean_kernel()
{
    int i = blockIdx.x * blockDim.x + threadIdx.x;
    if (i >= Tn*Sn*3) return;
    int st = i % 3, r = i / 3;
    int s = r & 3, t = r >> 2;
    float acc = 0.f;
    #pragma unroll
    for (int b = 0; b < Bb; b++)
        acc += g_g3[(((size_t)b*Tn + t)*Sn + s)*3 + st];
    g_g3m[i] = acc * 0.125f;
}

__global__ void state_scan_kernel()
{
    __shared__ float sm[12288];
    float ema = 0.5f; int cur = 0;
    for (int ph = 0; ph < 2; ph++) {
        __syncthreads();
        for (int i = threadIdx.x; i < 12288; i += blockDim.x) sm[i] = g_g3m[ph*12288 + i];
        __syncthreads();
        if (threadIdx.x < Sn) {
            int s = threadIdx.x;
            for (int tt = 0; tt < 1024; tt++) {
                int t = ph*1024 + tt;
                g_state[t*Sn + s] = cur;
                float gm = sm[(tt*Sn + s)*3 + cur];
                ema = 0.99f*ema + 0.01f*gm;
                if (cur == 0)      { if (ema < 0.1f)  cur = 1; }
                else if (cur == 1) { if (ema < 0.03f) cur = 2; else if (ema > 0.25f) cur = 0; }
                else               { if (ema > 0.25f) cur = 0; }
            }
        }
    }
}

__global__ void geff_kernel()
{
    int i = blockIdx.x * blockDim.x + threadIdx.x;
    if (i >= Mtot * Sn) return;
    int s = i & 3, m = i >> 2;
    int t = m & (Tn - 1);
    int st = g_state[t*Sn + s];
    float gn = (st == 0) ? 1.0f : ((st == 1) ? 0.5f : 0.1f);
    g_geff[i] = g_g3[(size_t)i*3 + st] * gn;
}

// ---------------- m recurrence: one thread per (b,s,d), unroll 16 ----------------
__global__ void mscan_kernel(const float* __restrict__ w0, float* __restrict__ out)
{
    int blk = blockIdx.x;              // 128 blocks x 128 threads
    int dchunk = blk & 3;
    int bs = blk >> 2;
    int s = bs & 3, b = bs >> 2;
    int d = dchunk*128 + threadIdx.x;

    const float* wp = g_wenc + ((size_t)s*Mtot + (size_t)b*Tn)*Dm + d;
    float* op = out + (size_t)b*Tn*(Sn*Dm) + s*Dm + d;
    const float* gp = g_geff + ((size_t)b*Tn)*Sn + s;

    float m = w0[s*Dm + d];
    for (int t0 = 0; t0 < Tn; t0 += 16) {
        float ge[16], w[16];
        #pragma unroll
        for (int u = 0; u < 16; u++) {
            ge[u] = __ldg(gp + (size_t)(t0+u)*Sn);
            w[u]  = __ldg(wp + (size_t)(t0+u)*Dm);
        }
        #pragma unroll
        for (int u = 0; u < 16; u++) {
            m = (1.f - ge[u])*m + ge[u]*w[u];
            op[(size_t)(t0+u)*(Sn*Dm)] = m;
        }
    }
}

// ---------------- launch ----------------
extern "C" void kernel_launch(void* const* d_in, const int* in_sizes, int n_in,
                              void* d_out, int out_size)
{
    const float* h        = (const float*)d_in[0];
    const float* pred_W   = (const float*)d_in[1];
    const float* pred_b   = (const float*)d_in[2];
    const float* gate_W1  = (const float*)d_in[3];
    const float* gate_b1  = (const float*)d_in[4];
    const float* gate_W2  = (const float*)d_in[5];
    const float* gate_b2  = (const float*)d_in[6];
    const float* write_W  = (const float*)d_in[7];
    const float* write_b  = (const float*)d_in[8];
    const float* w0       = (const float*)d_in[9];
    const float* st_embed = (const float*)d_in[10];
    float* out = (float*)d_out;

    const int smem0 = STAGES*(ATILE_B + 128*ROWB);   // 110592
    const int smem1 = STAGES*(ATILE_B + 64*ROWB);    // 82944
    static bool attr_done = false;
    if (!attr_done) {
        cudaFuncSetAttribute(gemm_mma<0>, cudaFuncAttributeMaxDynamicSharedMemorySize, smem0);
        cudaFuncSetAttribute(gemm_mma<1>, cudaFuncAttributeMaxDynamicSharedMemorySize, smem1);
        attr_done = true;
    }

    convA_kernel<<<(Mtot*Dm + 255)/256, 256>>>(h);
    convB_kernel<<<dim3(16, 34, Sn), dim3(32, 8)>>>(pred_W, write_W, gate_W1);
    zero_errsq_kernel<<<(Mtot*Sn + 255)/256, 256>>>();

    gemm_mma<0><<<dim3(8, 128, Sn), 256, smem0>>>(pred_b, write_b, gate_b1, h);
    gemm_mma<1><<<dim3(1, 128, Sn), 256, smem1>>>(pred_b, write_b, gate_b1, h);

    err_finalize_kernel<<<(Mtot*Sn + 255)/256, 256>>>();
    errmean_kernel<<<(Tn*Sn + 255)/256, 256>>>();
    scan_mu_kernel<<<1, 256>>>();
    mad_kernel<<<(Tn*Sn + 255)/256, 256>>>();
    scan_sigma_kernel<<<1, 256>>>();
    z_kernel<<<(Mtot*Sn + 255)/256, 256>>>();

    gate3_kernel<<<(Mtot*Sn*32 + 255)/256, 256>>>(gate_W1, gate_W2, gate_b2, st_embed);
    g3mean_kernel<<<(Tn*Sn*3 + 255)/256, 256>>>();
    state_scan_kernel<<<1, 256>>>();
    geff_kernel<<<(Mtot*Sn + 255)/256, 256>>>();

    mscan_kernel<<<128, 128>>>(w0, out);
}

// round 8
// speedup vs baseline: 3.2370x; 1.1231x over previous
#include <cuda_runtime.h>
#include <cuda_fp16.h>
#include <math.h>
#include <stdint.h>

#define Bb   8
#define Tn   2048
#define Dm   512
#define Sn   4
#define GH   64
#define Mtot (Bb*Tn)          // 16384
#define NROWS 1152            // 512 pred | 512 wenc | 64 gate | 64 zero-pad
#define KEXT  1024            // B: 512 hi | 512 lo
#define KA    512             // A: hi only

// ---------------- scratch (static device globals; zero-initialized) ----------------
__device__ __half g_Ahf[(size_t)Mtot*KA];          // [m][k] hi only
__device__ __half g_Bhf[(size_t)Sn*NROWS*KEXT];    // [s][n][k]; rows 1088.. stay zero
__device__ float g_wenc [(size_t)Sn*Mtot*Dm];
__device__ float g_hgate[(size_t)Sn*Mtot*GH];
__device__ float g_errsq[Mtot*Sn];
__device__ float g_err [Mtot*Sn];
__device__ float g_z   [Mtot*Sn];
__device__ float g_a   [Tn*Sn];
__device__ float g_mu  [Tn*Sn];
__device__ float g_mad [Tn*Sn];
__device__ float g_sig [Tn*Sn];
__device__ float g_g3  [(size_t)Mtot*Sn*3];
__device__ float g_g3m [Tn*Sn*3];
__device__ int   g_state[Tn*Sn];
__device__ float g_geff[Mtot*Sn];

// ---------------- prep: fp32 -> fp16 hi (A); also zero errsq ----------------
__global__ void convA_kernel(const float* __restrict__ h)
{
    int i = blockIdx.x * blockDim.x + threadIdx.x;
    if (i < Mtot*Sn) g_errsq[i] = 0.f;
    if (i >= Mtot * Dm) return;
    g_Ahf[i] = __float2half(h[i]);
}

// transpose [d][n] -> [n][d] via 32x33 smem tile; hi/lo split for B
__global__ void convB_kernel(const float* __restrict__ pred_W, const float* __restrict__ write_W,
                             const float* __restrict__ gate_W1)
{
    __shared__ float tile[32][33];
    const int s = blockIdx.z;
    const int n0 = blockIdx.y * 32;      // 0..1087
    const int d0 = blockIdx.x * 32;      // 0..511
    const int tx = threadIdx.x, ty = threadIdx.y;   // 32 x 8

    const float* src; int strideN, ncol;
    if (n0 < 512)       { src = pred_W  + (size_t)s*512*512; strideN = 512; ncol = n0 + tx; }
    else if (n0 < 1024) { src = write_W + (size_t)s*512*512; strideN = 512; ncol = n0 - 512 + tx; }
    else                { src = gate_W1 + (size_t)s*521*64;  strideN = 64;  ncol = n0 - 1024 + tx; }

    #pragma unroll
    for (int i = 0; i < 4; i++)
        tile[ty + 8*i][tx] = src[(size_t)(d0 + ty + 8*i)*strideN + ncol];
    __syncthreads();
    #pragma unroll
    for (int i = 0; i < 4; i++) {
        float v = tile[tx][ty + 8*i];
        __half hi = __float2half(v);
        __half lo = __float2half(v - __half2float(hi));
        size_t base = ((size_t)s*NROWS + n0 + ty + 8*i)*KEXT + d0 + tx;
        g_Bhf[base]       = hi;
        g_Bhf[base + 512] = lo;
    }
}

// ================= mma.sync helpers =================
__device__ __forceinline__ uint32_t smem_u32(const void* p) {
    uint32_t a;
    asm("{ .reg .u64 t; cvta.to.shared.u64 t, %1; cvt.u32.u64 %0, t; }" : "=r"(a) : "l"(p));
    return a;
}
#define CP16(dst, src) asm volatile("cp.async.cg.shared.global [%0], [%1], 16;" :: "r"(dst), "l"(src))
#define CP_COMMIT()    asm volatile("cp.async.commit_group;" ::: "memory")
#define CP_WAIT1()     asm volatile("cp.async.wait_group 1;" ::: "memory")
#define LDSM4(r0,r1,r2,r3,addr) \
    asm volatile("ldmatrix.sync.aligned.m8n8.x4.shared.b16 {%0,%1,%2,%3}, [%4];" \
        : "=r"(r0),"=r"(r1),"=r"(r2),"=r"(r3) : "r"(addr))
#define MMA16816(d, a, b) \
    asm volatile("mma.sync.aligned.m16n8k16.row.col.f32.f16.f16.f32 " \
        "{%0,%1,%2,%3},{%4,%5,%6,%7},{%8,%9},{%0,%1,%2,%3};" \
        : "+f"((d)[0]),"+f"((d)[1]),"+f"((d)[2]),"+f"((d)[3]) \
        : "r"((a)[0]),"r"((a)[1]),"r"((a)[2]),"r"((a)[3]), "r"((b)[0]),"r"((b)[1]))

#define PITCH    72
#define ROWB     (PITCH*2)          // 144 bytes per row
#define ATILE_B  (128*ROWB)         // 18432 bytes
#define BTILE_B  (128*ROWB)
#define STAGES   3
#define GEMM_SMEM (STAGES*(ATILE_B + BTILE_B))   // 110592

// blockIdx.x: 0..3 preds (1-pass), 4..7 wenc (2-pass), 8 gate (2-pass)
__global__ void __launch_bounds__(256, 2)
gemm_mma(const float* __restrict__ pred_b, const float* __restrict__ write_b,
         const float* __restrict__ gate_b1, const float* __restrict__ hseq)
{
    extern __shared__ __align__(16) char smem[];
    const uint32_t sAu = smem_u32(smem);
    const uint32_t sBu = sAu + STAGES*ATILE_B;

    const int tid = threadIdx.x;
    const int wid = tid >> 5, lane = tid & 31;
    const int s = blockIdx.z;
    const int mbase = blockIdx.y * 128;

    int which, nbase, colbase, NT;
    {
        const int x = blockIdx.x;
        if (x < 4)      { which = 0; nbase = x*128;           colbase = x*128;       NT = 8;  }
        else if (x < 8) { which = 1; nbase = 512 + (x-4)*128; colbase = (x-4)*128;   NT = 16; }
        else            { which = 2; nbase = 1024;            colbase = 0;           NT = 16; }
    }

    const int mw = wid >> 2, nw = wid & 3;
    const int m0 = mw * 64;
    const int n0 = nw * 32;

    const int idx = lane & 7, sel = lane >> 3;
    const uint32_t aAddrBase = sAu + (uint32_t)(m0 + (sel&1)*8 + idx) * ROWB + (uint32_t)((sel>>1)*8)*2;
    const uint32_t bAddrBase = sBu + (uint32_t)(n0 + (sel>>1)*8 + idx) * ROWB + (uint32_t)((sel&1)*8)*2;

    float acc[4][4][4];
    #pragma unroll
    for (int i = 0; i < 4; i++)
        #pragma unroll
        for (int j = 0; j < 4; j++)
            #pragma unroll
            for (int q = 0; q < 4; q++) acc[i][j][q] = 0.f;

    const char* Aall = (const char*)g_Ahf;
    const char* Ball = (const char*)g_Bhf;

    // chunk c: A col = (c&7)*64 (hi only); B col = (c>>3)*512 + (c&7)*64 (hi then lo)
    auto load_tile = [&](int c, int slot) {
        const int acol = (c & 7) * 64;
        const int bcol = ((c >> 3) ? 512 : 0) + (c & 7) * 64;
        const uint32_t ab = sAu + slot * ATILE_B;
        const uint32_t bb = sBu + slot * BTILE_B;
        #pragma unroll
        for (int it = 0; it < 4; it++) {
            int g = tid + it*256;                 // 1024 granules: row*8 + gc
            int row = g >> 3, gc = g & 7;
            CP16(ab + row*ROWB + gc*16,
                 Aall + ((size_t)(mbase + row)*KA + acol + gc*8)*2);
        }
        #pragma unroll
        for (int it = 0; it < 4; it++) {
            int g = tid + it*256;
            int row = g >> 3, gc = g & 7;
            CP16(bb + row*ROWB + gc*16,
                 Ball + (((size_t)s*NROWS + nbase + row)*KEXT + bcol + gc*8)*2);
        }
        CP_COMMIT();
    };

    load_tile(0, 0);
    load_tile(1, 1);
    int slot = 0;
    for (int c = 0; c < NT; c++) {
        CP_WAIT1();
        __syncthreads();
        if (c + 2 < NT) load_tile(c + 2, (c + 2) % STAGES);
        else CP_COMMIT();
        const uint32_t aOff = aAddrBase + slot*ATILE_B;
        const uint32_t bOff = bAddrBase + slot*BTILE_B;
        #pragma unroll
        for (int ks = 0; ks < 4; ks++) {
            uint32_t afr[4][4], bfr[4][2];
            #pragma unroll
            for (int i = 0; i < 4; i++)
                LDSM4(afr[i][0], afr[i][1], afr[i][2], afr[i][3],
                      aOff + i*16*ROWB + ks*32);
            #pragma unroll
            for (int jp = 0; jp < 2; jp++) {
                uint32_t r0, r1, r2, r3;
                LDSM4(r0, r1, r2, r3, bOff + jp*16*ROWB + ks*32);
                bfr[jp*2+0][0] = r0; bfr[jp*2+0][1] = r1;
                bfr[jp*2+1][0] = r2; bfr[jp*2+1][1] = r3;
            }
            #pragma unroll
            for (int i = 0; i < 4; i++)
                #pragma unroll
                for (int j = 0; j < 4; j++)
                    MMA16816(acc[i][j], afr[i], bfr[j]);
        }
        slot = (slot + 1 == STAGES) ? 0 : slot + 1;
    }

    // ---------------- epilogue ----------------
    const int rbase = mbase + m0 + (lane >> 2);
    const int cbase = colbase + n0 + (lane & 3) * 2;

    if (which == 0) {
        // fused err: sum (pred - h[r+1])^2, atomic into g_errsq
        const float* bias = pred_b + s*Dm;
        float rowsum[4][2];
        #pragma unroll
        for (int i = 0; i < 4; i++) { rowsum[i][0] = 0.f; rowsum[i][1] = 0.f; }
        #pragma unroll
        for (int j = 0; j < 4; j++) {
            const int col = cbase + j*8;
            const float b0 = __ldg(bias + col), b1 = __ldg(bias + col + 1);
            #pragma unroll
            for (int i = 0; i < 4; i++) {
                const int r1 = rbase + i*16, r2 = r1 + 8;
                float2 h1 = *(const float2*)(hseq + (size_t)(r1+1)*Dm + col);
                float2 h2 = *(const float2*)(hseq + (size_t)(r2+1)*Dm + col);
                float d0 = acc[i][j][0] + b0 - h1.x;
                float d1 = acc[i][j][1] + b1 - h1.y;
                float d2 = acc[i][j][2] + b0 - h2.x;
                float d3 = acc[i][j][3] + b1 - h2.y;
                rowsum[i][0] += d0*d0 + d1*d1;
                rowsum[i][1] += d2*d2 + d3*d3;
            }
        }
        #pragma unroll
        for (int i = 0; i < 4; i++) {
            #pragma unroll
            for (int hh = 0; hh < 2; hh++) {
                float v = rowsum[i][hh];
                v += __shfl_xor_sync(0xffffffffu, v, 1);
                v += __shfl_xor_sync(0xffffffffu, v, 2);
                if ((lane & 3) == 0) {
                    int r = rbase + i*16 + hh*8;
                    if ((r & (Tn - 1)) != Tn - 1)
                        atomicAdd(&g_errsq[(r + 1)*Sn + s], v);
                }
            }
        }
        return;
    }

    if (which == 2 && n0 >= GH) return;   // gate tile: only cols 0..63 valid

    float* Cm; const float* bias; int stride;
    if (which == 1) { Cm = g_wenc + (size_t)s*Mtot*Dm; bias = write_b + s*Dm; stride = Dm; }
    else            { Cm = g_hgate + (size_t)s*Mtot*GH; bias = gate_b1 + s*GH; stride = GH; }

    #pragma unroll
    for (int j = 0; j < 4; j++) {
        const int col = cbase + j*8;
        const float b0 = __ldg(bias + col), b1 = __ldg(bias + col + 1);
        #pragma unroll
        for (int i = 0; i < 4; i++) {
            const int r = rbase + i*16;
            float2 o0 = { acc[i][j][0] + b0, acc[i][j][1] + b1 };
            float2 o1 = { acc[i][j][2] + b0, acc[i][j][3] + b1 };
            *(float2*)(Cm + (size_t)r*stride + col)       = o0;
            *(float2*)(Cm + (size_t)(r+8)*stride + col)   = o1;
        }
    }
}

// ---------------- err finalize: sqrt(sum + 1e-8), 0 at t=0 ----------------
__global__ void err_finalize_kernel()
{
    int i = blockIdx.x * blockDim.x + threadIdx.x;
    if (i >= Mtot * Sn) return;
    int t = (i >> 2) & (Tn - 1);
    g_err[i] = (t == 0) ? 0.f : sqrtf(g_errsq[i] + 1e-8f);
}

__global__ void errmean_kernel()
{
    int i = blockIdx.x * blockDim.x + threadIdx.x;
    if (i >= Tn * Sn) return;
    int s = i & 3, t = i >> 2;
    float acc = 0.f;
    #pragma unroll
    for (int b = 0; b < Bb; b++) acc += g_err[((size_t)(b*Tn + t))*Sn + s];
    g_a[i] = acc * 0.125f;
}

__global__ void scan_mu_kernel()
{
    __shared__ float sm[Tn*Sn];
    for (int i = threadIdx.x; i < Tn*Sn; i += blockDim.x) sm[i] = g_a[i];
    __syncthreads();
    if (threadIdx.x < Sn) {
        int s = threadIdx.x;
        float mu = 0.f;
        for (int t = 0; t < Tn; t++) {
            g_mu[t*Sn + s] = mu;
            if (t > 0) mu = 0.99f*mu + 0.01f*sm[t*Sn + s];
        }
    }
}

__global__ void mad_kernel()
{
    int i = blockIdx.x * blockDim.x + threadIdx.x;
    if (i >= Tn * Sn) return;
    int s = i & 3, t = i >> 2;
    float mu = g_mu[i];
    float acc = 0.f;
    #pragma unroll
    for (int b = 0; b < Bb; b++) acc += fabsf(g_err[((size_t)(b*Tn + t))*Sn + s] - mu);
    g_mad[i] = acc * 0.125f;
}

__global__ void scan_sigma_kernel()
{
    __shared__ float sm[Tn*Sn];
    for (int i = threadIdx.x; i < Tn*Sn; i += blockDim.x) sm[i] = g_mad[i];
    __syncthreads();
    if (threadIdx.x < Sn) {
        int s = threadIdx.x;
        float sg = 1.f;
        for (int t = 0; t < Tn; t++) {
            g_sig[t*Sn + s] = sg;
            if (t > 0) sg = 0.99f*sg + 0.01f*sm[t*Sn + s];
        }
    }
}

__global__ void z_kernel()
{
    int i = blockIdx.x * blockDim.x + threadIdx.x;
    if (i >= Mtot * Sn) return;
    int s = i & 3, m = i >> 2;
    int t = m & (Tn - 1);
    g_z[i] = (t == 0) ? 0.f
                      : (g_err[i] - g_mu[t*Sn + s]) / fmaxf(g_sig[t*Sn + s], 1e-3f);
}

// ---------------- gate for all 3 hypothetical states ----------------
__global__ void gate3_kernel(const float* __restrict__ gate_W1, const float* __restrict__ gate_W2,
                             const float* __restrict__ gate_b2, const float* __restrict__ se)
{
    int gw = (blockIdx.x * blockDim.x + threadIdx.x) >> 5;
    int lane = threadIdx.x & 31;
    if (gw >= Mtot * Sn) return;
    int s = gw & 3, m = gw >> 2;
    const float* W1 = gate_W1 + (size_t)s * 521 * GH;
    const float* hb = g_hgate + ((size_t)s*Mtot + m) * GH;
    float zz = g_z[m*Sn + s];
    float base0 = hb[lane]      + zz * W1[512*GH + lane];
    float base1 = hb[lane + 32] + zz * W1[512*GH + lane + 32];
    float se0[3] = {0,0,0}, se1[3] = {0,0,0};
    #pragma unroll
    for (int e = 0; e < 8; e++) {
        float wa = W1[(513+e)*GH + lane];
        float wb = W1[(513+e)*GH + lane + 32];
        #pragma unroll
        for (int st = 0; st < 3; st++) {
            float sv = se[st*8 + e];
            se0[st] += sv * wa; se1[st] += sv * wb;
        }
    }
    float w20 = gate_W2[s*GH + lane], w21 = gate_W2[s*GH + lane + 32];
    float b2 = gate_b2[s];
    #pragma unroll
    for (int st = 0; st < 3; st++) {
        float v = fmaxf(base0 + se0[st], 0.f)*w20 + fmaxf(base1 + se1[st], 0.f)*w21;
        #pragma unroll
        for (int o = 16; o; o >>= 1) v += __shfl_down_sync(0xffffffffu, v, o);
        if (!lane) g_g3[((size_t)m*Sn + s)*3 + st] = 1.f / (1.f + expf(-(v + b2)));
    }
}

__global__ void g3mean_kernel()
{
    int i = blockIdx.x * blockDim.x + threadIdx.x;
    if (i >= Tn*Sn*3) return;
    int st = i % 3, r = i / 3;
    int s = r & 3, t = r >> 2;
    float acc = 0.f;
    #pragma unroll
    for (int b = 0; b < Bb; b++)
        acc += g_g3[(((size_t)b*Tn + t)*Sn + s)*3 + st];
    g_g3m[i] = acc * 0.125f;
}

__global__ void state_scan_kernel()
{
    __shared__ float sm[12288];
    float ema = 0.5f; int cur = 0;
    for (int ph = 0; ph < 2; ph++) {
        __syncthreads();
        for (int i = threadIdx.x; i < 12288; i += blockDim.x) sm[i] = g_g3m[ph*12288 + i];
        __syncthreads();
        if (threadIdx.x < Sn) {
            int s = threadIdx.x;
            for (int tt = 0; tt < 1024; tt++) {
                int t = ph*1024 + tt;
                g_state[t*Sn + s] = cur;
                float gm = sm[(tt*Sn + s)*3 + cur];
                ema = 0.99f*ema + 0.01f*gm;
                if (cur == 0)      { if (ema < 0.1f)  cur = 1; }
                else if (cur == 1) { if (ema < 0.03f) cur = 2; else if (ema > 0.25f) cur = 0; }
                else               { if (ema > 0.25f) cur = 0; }
            }
        }
    }
}

__global__ void geff_kernel()
{
    int i = blockIdx.x * blockDim.x + threadIdx.x;
    if (i >= Mtot * Sn) return;
    int s = i & 3, m = i >> 2;
    int t = m & (Tn - 1);
    int st = g_state[t*Sn + s];
    float gn = (st == 0) ? 1.0f : ((st == 1) ? 0.5f : 0.1f);
    g_geff[i] = g_g3[(size_t)i*3 + st] * gn;
}

// ---------------- m recurrence: one thread per (b,s,d), unroll 16 ----------------
__global__ void mscan_kernel(const float* __restrict__ w0, float* __restrict__ out)
{
    int blk = blockIdx.x;              // 128 blocks x 128 threads
    int dchunk = blk & 3;
    int bs = blk >> 2;
    int s = bs & 3, b = bs >> 2;
    int d = dchunk*128 + threadIdx.x;

    const float* wp = g_wenc + ((size_t)s*Mtot + (size_t)b*Tn)*Dm + d;
    float* op = out + (size_t)b*Tn*(Sn*Dm) + s*Dm + d;
    const float* gp = g_geff + ((size_t)b*Tn)*Sn + s;

    float m = w0[s*Dm + d];
    for (int t0 = 0; t0 < Tn; t0 += 16) {
        float ge[16], w[16];
        #pragma unroll
        for (int u = 0; u < 16; u++) {
            ge[u] = __ldg(gp + (size_t)(t0+u)*Sn);
            w[u]  = __ldg(wp + (size_t)(t0+u)*Dm);
        }
        #pragma unroll
        for (int u = 0; u < 16; u++) {
            m = (1.f - ge[u])*m + ge[u]*w[u];
            op[(size_t)(t0+u)*(Sn*Dm)] = m;
        }
    }
}

// ---------------- launch ----------------
extern "C" void kernel_launch(void* const* d_in, const int* in_sizes, int n_in,
                              void* d_out, int out_size)
{
    const float* h        = (const float*)d_in[0];
    const float* pred_W   = (const float*)d_in[1];
    const float* pred_b   = (const float*)d_in[2];
    const float* gate_W1  = (const float*)d_in[3];
    const float* gate_b1  = (const float*)d_in[4];
    const float* gate_W2  = (const float*)d_in[5];
    const float* gate_b2  = (const float*)d_in[6];
    const float* write_W  = (const float*)d_in[7];
    const float* write_b  = (const float*)d_in[8];
    const float* w0       = (const float*)d_in[9];
    const float* st_embed = (const float*)d_in[10];
    float* out = (float*)d_out;

    static bool attr_done = false;
    if (!attr_done) {
        cudaFuncSetAttribute(gemm_mma, cudaFuncAttributeMaxDynamicSharedMemorySize, GEMM_SMEM);
        attr_done = true;
    }

    convA_kernel<<<(Mtot*Dm + 255)/256, 256>>>(h);
    convB_kernel<<<dim3(16, 34, Sn), dim3(32, 8)>>>(pred_W, write_W, gate_W1);

    gemm_mma<<<dim3(9, 128, Sn), 256, GEMM_SMEM>>>(pred_b, write_b, gate_b1, h);

    err_finalize_kernel<<<(Mtot*Sn + 255)/256, 256>>>();
    errmean_kernel<<<(Tn*Sn + 255)/256, 256>>>();
    scan_mu_kernel<<<1, 256>>>();
    mad_kernel<<<(Tn*Sn + 255)/256, 256>>>();
    scan_sigma_kernel<<<1, 256>>>();
    z_kernel<<<(Mtot*Sn + 255)/256, 256>>>();

    gate3_kernel<<<(Mtot*Sn*32 + 255)/256, 256>>>(gate_W1, gate_W2, gate_b2, st_embed);
    g3mean_kernel<<<(Tn*Sn*3 + 255)/256, 256>>>();
    state_scan_kernel<<<1, 256>>>();
    geff_kernel<<<(Mtot*Sn + 255)/256, 256>>>();

    mscan_kernel<<<128, 128>>>(w0, out);
}